// round 13
// baseline (speedup 1.0000x reference)
#include <cuda_runtime.h>
#include <cuda_bf16.h>
#include <math.h>
#include <stdint.h>

#define BB 8
#define MM 1024
#define DD 1024
#define HH 16
#define KHD 64
#define N3 3072
#define KQ 256   // k-quads (4 int8) for K=1024

// fp32 attention output (quantized by a pass before proj)
__device__ float g_O[BB*MM*DD];

// int8 Ozaki operands for projections: u32 = 4 consecutive-k int8
__device__ uint32_t g_xH [BB*MM*KQ],  g_xL [BB*MM*KQ];
__device__ float    g_xS [BB*MM];
__device__ uint32_t g_PiH[N3*KQ],     g_PiL[N3*KQ];
__device__ float    g_PiS[N3];
__device__ uint32_t g_PoH[DD*KQ],     g_PoL[DD*KQ];
__device__ float    g_PoS[DD];
__device__ uint32_t g_OH [BB*MM*KQ],  g_OL [BB*MM*KQ];
__device__ float    g_OS [BB*MM];

// int8 attention operands (rows of 64 -> 16 kq)
__device__ uint32_t g_QH[BB*HH*MM*16], g_QL[BB*HH*MM*16];
__device__ float    g_QS[BB*HH*MM];
__device__ uint32_t g_KH[BB*HH*MM*16], g_KL[BB*HH*MM*16];
__device__ float    g_KS[BB*HH*MM];

// bf16 V operands (packed bf16x2 key-pairs, transposed [bh][d][mp])
__device__ uint32_t g_Vph[BB*HH*KHD*(MM/2)], g_Vpl[BB*HH*KHD*(MM/2)];

// ---------------------------------------------------------------------------
__device__ __forceinline__ uint32_t bpack(float x, float y){
    __nv_bfloat162 h = __floats2bfloat162_rn(x, y);
    return *reinterpret_cast<uint32_t*>(&h);
}
__device__ __forceinline__ uint32_t bsplit(float x, float y, float& rx, float& ry){
    __nv_bfloat162 h = __floats2bfloat162_rn(x, y);
    rx = x - __low2float(h);
    ry = y - __high2float(h);
    return *reinterpret_cast<uint32_t*>(&h);
}
__device__ __forceinline__ void mma16(float* d, const uint32_t* a,
                                      uint32_t b0, uint32_t b1){
    asm volatile("mma.sync.aligned.m16n8k16.row.col.f32.bf16.bf16.f32 "
        "{%0,%1,%2,%3},{%4,%5,%6,%7},{%8,%9},{%0,%1,%2,%3};"
        : "+f"(d[0]), "+f"(d[1]), "+f"(d[2]), "+f"(d[3])
        : "r"(a[0]), "r"(a[1]), "r"(a[2]), "r"(a[3]), "r"(b0), "r"(b1));
}
__device__ __forceinline__ void imma32(int* d, const uint32_t* a,
                                       uint32_t b0, uint32_t b1){
    asm volatile("mma.sync.aligned.m16n8k32.row.col.s32.s8.s8.s32 "
        "{%0,%1,%2,%3},{%4,%5,%6,%7},{%8,%9},{%0,%1,%2,%3};"
        : "+r"(d[0]), "+r"(d[1]), "+r"(d[2]), "+r"(d[3])
        : "r"(a[0]), "r"(a[1]), "r"(a[2]), "r"(a[3]), "r"(b0), "r"(b1));
}
__device__ __forceinline__ uint32_t smem_u32(const void* p){
    uint32_t a;
    asm("{ .reg .u64 t; cvta.to.shared.u64 t, %1; cvt.u32.u64 %0, t; }"
        : "=r"(a) : "l"(p));
    return a;
}
__device__ __forceinline__ void cpa16(uint32_t dst, const void* src){
    asm volatile("cp.async.ca.shared.global [%0], [%1], 16;"
                 :: "r"(dst), "l"(src) : "memory");
}
#define CP_COMMIT() asm volatile("cp.async.commit_group;" ::: "memory")
#define CP_WAIT1()  asm volatile("cp.async.wait_group 1;" ::: "memory")
#define CP_WAIT0()  asm volatile("cp.async.wait_group 0;" ::: "memory")
#define LDSM4(r0,r1,r2,r3,addr) asm volatile( \
    "ldmatrix.sync.aligned.m8n8.x4.shared.b16 {%0,%1,%2,%3}, [%4];" \
    : "=r"(r0), "=r"(r1), "=r"(r2), "=r"(r3) : "r"(addr))

__device__ __forceinline__ uint32_t pack4(int a, int b, int c, int d){
    return (uint32_t)(uint8_t)(int8_t)a        | ((uint32_t)(uint8_t)(int8_t)b << 8)
         | ((uint32_t)(uint8_t)(int8_t)c << 16)| ((uint32_t)(uint8_t)(int8_t)d << 24);
}
__device__ __forceinline__ void q2(float f, float inv, int& h, int& l){
    float q = f * inv;
    h = __float2int_rn(q);
    l = __float2int_rn((q - (float)h) * 128.f);
}

// ---------------------------------------------------------------------------
// Quantization pre-passes (x, weights, O)
// ---------------------------------------------------------------------------
__global__ void quant_rows(const float* __restrict__ src,
                           uint32_t* __restrict__ H, uint32_t* __restrict__ L,
                           float* __restrict__ S){
    __shared__ float red[256];
    const int row = blockIdx.x, tid = threadIdx.x;
    float4 v = ((const float4*)(src + (size_t)row*1024))[tid];
    float m = fmaxf(fmaxf(fabsf(v.x), fabsf(v.y)), fmaxf(fabsf(v.z), fabsf(v.w)));
    red[tid] = m; __syncthreads();
    for (int o = 128; o > 0; o >>= 1){
        if (tid < o) red[tid] = fmaxf(red[tid], red[tid+o]);
        __syncthreads();
    }
    const float s = fmaxf(red[0], 1e-20f);
    const float inv = 127.f / s;
    int h0,l0,h1,l1,h2,l2,h3,l3;
    q2(v.x, inv, h0, l0); q2(v.y, inv, h1, l1);
    q2(v.z, inv, h2, l2); q2(v.w, inv, h3, l3);
    H[(size_t)row*KQ + tid] = pack4(h0,h1,h2,h3);
    L[(size_t)row*KQ + tid] = pack4(l0,l1,l2,l3);
    if (tid == 0) S[row] = s;
}
__global__ void colmax(const float* __restrict__ W, float* __restrict__ S, int N){
    int n = blockIdx.x*256 + threadIdx.x;
    if (n >= N) return;
    float m = 0.f;
    for (int k = 0; k < 1024; k++) m = fmaxf(m, fabsf(W[(size_t)k*N + n]));
    S[n] = fmaxf(m, 1e-20f);
}
__global__ void quant_wT(const float* __restrict__ W,
                         uint32_t* __restrict__ H, uint32_t* __restrict__ L,
                         const float* __restrict__ S, int N){
    __shared__ float tile[64][33];
    const int n0 = blockIdx.x*32, k0 = blockIdx.y*64, tid = threadIdx.x;
    #pragma unroll
    for (int it = 0; it < 8; it++){
        int idx = tid + it*256;
        int kr = idx >> 5, nc = idx & 31;
        tile[kr][nc] = W[(size_t)(k0+kr)*N + n0 + nc];
    }
    __syncthreads();
    const int nl = tid >> 3, kq8 = tid & 7;
    const float inv = 127.f / S[n0 + nl];
    #pragma unroll
    for (int j = 0; j < 2; j++){
        int kq = kq8*2 + j;
        int h0,l0,h1,l1,h2,l2,h3,l3;
        q2(tile[kq*4+0][nl], inv, h0, l0);
        q2(tile[kq*4+1][nl], inv, h1, l1);
        q2(tile[kq*4+2][nl], inv, h2, l2);
        q2(tile[kq*4+3][nl], inv, h3, l3);
        H[(size_t)(n0+nl)*KQ + blockIdx.y*16 + kq] = pack4(h0,h1,h2,h3);
        L[(size_t)(n0+nl)*KQ + blockIdx.y*16 + kq] = pack4(l0,l1,l2,l3);
    }
}

// ---------------------------------------------------------------------------
// int8 Ozaki GEMM. MODE 1: QKV — each bn tile (64 cols) is exactly one of
// Q/K/V for one head (head stride 192 = 3*64). Epilogue stages fp32 block in
// smem, then: Q/K -> per-row-of-64 int8 quant (same numerics as old
// quant_qk64); V -> bf16 hi/lo split + transpose to [d][mp]. MODE 2: proj.
// ---------------------------------------------------------------------------
#define GI_STAGE 7680
#define GI_SMEM_BYTES (2*GI_STAGE*4)

template<int MODE>
__global__ __launch_bounds__(256, 2) void gemm_i8(
    const uint32_t* __restrict__ AH, const uint32_t* __restrict__ AL,
    const uint32_t* __restrict__ BH, const uint32_t* __restrict__ BL,
    const float* __restrict__ SA, const float* __restrict__ SB,
    float* __restrict__ C, int Mx, int Nx)
{
    extern __shared__ uint32_t smg[];
    const uint32_t sb = smem_u32(smg);
    const int tid = threadIdx.x, lane = tid & 31, wid = tid >> 5;
    const int wm = wid >> 2, wn = wid & 3;
    const int bm = blockIdx.y, bn = blockIdx.x, bz = blockIdx.z;

    const uint32_t* Ah = AH + (size_t)bz * Mx * KQ;
    const uint32_t* Al = AL + (size_t)bz * Mx * KQ;

    auto issue = [&](int t){
        const int kq0 = t << 4;
        const uint32_t d0 = sb + ((t & 1)*GI_STAGE)*4;
        #pragma unroll
        for (int it = 0; it < 2; it++){
            int idx = tid + it*256;
            int ra = idx >> 2, ca = (idx & 3) << 2;
            cpa16(d0 + (ra*20 + ca)*4,          Ah + (size_t)(bm*128 + ra)*KQ + kq0 + ca);
            cpa16(d0 + (2560 + ra*20 + ca)*4,   Al + (size_t)(bm*128 + ra)*KQ + kq0 + ca);
        }
        {
            int rb = tid >> 2, cb = (tid & 3) << 2;
            cpa16(d0 + (5120 + rb*20 + cb)*4,   BH + (size_t)(bn*64 + rb)*KQ + kq0 + cb);
            cpa16(d0 + (6400 + rb*20 + cb)*4,   BL + (size_t)(bn*64 + rb)*KQ + kq0 + cb);
        }
        CP_COMMIT();
    };

    int hh[4][2][4], xx[4][2][4];
    #pragma unroll
    for (int mt = 0; mt < 4; mt++)
        #pragma unroll
        for (int nt = 0; nt < 2; nt++)
            #pragma unroll
            for (int c = 0; c < 4; c++){ hh[mt][nt][c] = 0; xx[mt][nt][c] = 0; }

    const uint32_t lrow = (lane & 15), lcolo = ((lane >> 4) << 2);
    const int nT = 16;

    issue(0);
    for (int t = 0; t < nT; ++t){
        CP_WAIT0();
        __syncthreads();
        if (t + 1 < nT) issue(t + 1);

        const uint32_t st = sb + ((t & 1)*GI_STAGE)*4;
        #pragma unroll
        for (int kk = 0; kk < 2; kk++){
            const uint32_t fo = (lrow*20 + kk*8 + lcolo)*4;
            uint32_t aH_[4][4], aL_[4][4];
            #pragma unroll
            for (int mt = 0; mt < 4; mt++){
                const uint32_t ra = st + ((wm*64 + mt*16)*20)*4 + fo;
                LDSM4(aH_[mt][0], aH_[mt][1], aH_[mt][2], aH_[mt][3], ra);
                LDSM4(aL_[mt][0], aL_[mt][1], aL_[mt][2], aL_[mt][3], ra + 2560*4);
            }
            const uint32_t rb = st + (5120 + (wn*16)*20)*4 + fo;
            uint32_t bH0, bH1, bH2, bH3, bL0, bL1, bL2, bL3;
            LDSM4(bH0, bH1, bH2, bH3, rb);
            LDSM4(bL0, bL1, bL2, bL3, rb + 1280*4);
            #pragma unroll
            for (int mt = 0; mt < 4; mt++){
                imma32(hh[mt][0], aH_[mt], bH0, bH2);
                imma32(xx[mt][0], aH_[mt], bL0, bL2);
                imma32(xx[mt][0], aL_[mt], bH0, bH2);
                imma32(hh[mt][1], aH_[mt], bH1, bH3);
                imma32(xx[mt][1], aH_[mt], bL1, bL3);
                imma32(xx[mt][1], aL_[mt], bH1, bH3);
            }
        }
    }

    if (MODE == 2){
        #pragma unroll
        for (int mt = 0; mt < 4; mt++)
            #pragma unroll
            for (int nt = 0; nt < 2; nt++){
                const int col0 = bn*64 + wn*16 + nt*8 + ((lane&3)<<1);
                const float t0 = SB[col0], t1 = SB[col0+1];
                #pragma unroll
                for (int half = 0; half < 2; half++){
                    const int row = bm*128 + wm*64 + mt*16 + (lane>>2) + half*8;
                    const float s = SA[row];
                    const float c0 = s*t0*(1.f/16129.f), c1 = s*t1*(1.f/16129.f);
                    const float v0 = c0*((float)hh[mt][nt][2*half]   + (float)xx[mt][nt][2*half]  *(1.f/128.f));
                    const float v1 = c1*((float)hh[mt][nt][2*half+1] + (float)xx[mt][nt][2*half+1]*(1.f/128.f));
                    *(float2*)&C[(size_t)row*Nx + col0] = make_float2(v0, v1);
                }
            }
        return;
    }

    // -------- MODE 1: fused Q/K quant or V split epilogue --------
    float* Fs = (float*)smg;   // [128][66] fp32 stage (33.8 KB <= 60 KB)
    __syncthreads();           // all warps done with pipeline smem
    #pragma unroll
    for (int mt = 0; mt < 4; mt++)
        #pragma unroll
        for (int nt = 0; nt < 2; nt++){
            const int colL = wn*16 + nt*8 + ((lane&3)<<1);
            const int colG = bn*64 + colL;
            const float t0 = SB[colG], t1 = SB[colG+1];
            #pragma unroll
            for (int half = 0; half < 2; half++){
                const int rowL = wm*64 + mt*16 + (lane>>2) + half*8;
                const float s = SA[(size_t)bz*Mx + bm*128 + rowL];
                const float c0 = s*t0*(1.f/16129.f), c1 = s*t1*(1.f/16129.f);
                Fs[rowL*66 + colL]     = c0*((float)hh[mt][nt][2*half]   + (float)xx[mt][nt][2*half]  *(1.f/128.f));
                Fs[rowL*66 + colL + 1] = c1*((float)hh[mt][nt][2*half+1] + (float)xx[mt][nt][2*half+1]*(1.f/128.f));
            }
        }
    __syncthreads();

    const int hHead = bn / 3;
    const int kind = bn - 3*hHead;        // 0=Q, 1=K, 2=V
    if (kind < 2){
        uint32_t* Hd = kind ? g_KH : g_QH;
        uint32_t* Ld = kind ? g_KL : g_QL;
        float*    Sd = kind ? g_KS : g_QS;
        // warp wid handles rows wid*16..+15
        for (int r = 0; r < 16; r++){
            const int row = wid*16 + r;
            const float a = Fs[row*66 + 2*lane];
            const float b = Fs[row*66 + 2*lane + 1];
            float m = fmaxf(fabsf(a), fabsf(b));
            #pragma unroll
            for (int o = 16; o > 0; o >>= 1)
                m = fmaxf(m, __shfl_xor_sync(0xffffffffu, m, o));
            const float s = fmaxf(m, 1e-20f);
            const size_t mi = (size_t)(bz*HH + hHead)*MM + bm*128 + row;
            if (lane == 0) Sd[mi] = s;
            if (lane < 16){
                const float inv = 127.f / s;
                int h0,l0,h1,l1,h2,l2,h3,l3;
                q2(Fs[row*66 + 4*lane + 0], inv, h0, l0);
                q2(Fs[row*66 + 4*lane + 1], inv, h1, l1);
                q2(Fs[row*66 + 4*lane + 2], inv, h2, l2);
                q2(Fs[row*66 + 4*lane + 3], inv, h3, l3);
                Hd[mi*16 + lane] = pack4(h0,h1,h2,h3);
                Ld[mi*16 + lane] = pack4(l0,l1,l2,l3);
            }
        }
    } else {
        // V: bf16 split + transpose -> [d][mp] pairs
        uint32_t* oh = g_Vph + (size_t)(bz*HH + hHead)*KHD*(MM/2);
        uint32_t* ol = g_Vpl + (size_t)(bz*HH + hHead)*KHD*(MM/2);
        const int d = tid >> 2;
        #pragma unroll
        for (int j = 0; j < 16; j++){
            const int i = (tid & 3)*16 + j;   // local mp 0..63
            const float a = Fs[(2*i)*66 + d];
            const float b = Fs[(2*i+1)*66 + d];
            float rx, ry;
            const uint32_t hv = bsplit(a, b, rx, ry);
            oh[(size_t)d*(MM/2) + bm*64 + i] = hv;
            ol[(size_t)d*(MM/2) + bm*64 + i] = bpack(rx, ry);
        }
    }
}

// ---------------------------------------------------------------------------
// Flash attention: S = QK^T int8 Ozaki, softmax fp32, P.V bf16 3x (as R12).
// ---------------------------------------------------------------------------
#define A_STAGE 7232
#define ATTN_SMEM_BYTES (3*A_STAGE*4)

__global__ __launch_bounds__(256, 2) void attn_tc()
{
    extern __shared__ uint32_t smu[];
    const uint32_t sb = smem_u32(smu);

    const int tid = threadIdx.x, lane = tid & 31, wid = tid >> 5;
    const int qt = gridDim.x - 1 - blockIdx.x;
    const int bh = blockIdx.y;
    const int q0 = qt * 128;

    const uint32_t* KH_g = g_KH + (size_t)bh*MM*16;
    const uint32_t* KL_g = g_KL + (size_t)bh*MM*16;
    const float*    KS_g = g_KS + (size_t)bh*MM;
    const uint32_t* Vh_g = g_Vph + (size_t)bh*KHD*(MM/2);
    const uint32_t* Vl_g = g_Vpl + (size_t)bh*KHD*(MM/2);

    const int rA = wid*16 + (lane>>2);
    const size_t qrow = (size_t)bh*MM + q0 + rA;

    uint32_t qH[2][4], qL[2][4];
    #pragma unroll
    for (int ks = 0; ks < 2; ks++){
        int kq = ks*8 + (lane & 3);
        qH[ks][0] = g_QH[qrow*16 + kq];
        qH[ks][1] = g_QH[(qrow+8)*16 + kq];
        qH[ks][2] = g_QH[qrow*16 + kq + 4];
        qH[ks][3] = g_QH[(qrow+8)*16 + kq + 4];
        qL[ks][0] = g_QL[qrow*16 + kq];
        qL[ks][1] = g_QL[(qrow+8)*16 + kq];
        qL[ks][2] = g_QL[qrow*16 + kq + 4];
        qL[ks][3] = g_QL[(qrow+8)*16 + kq + 4];
    }
    const float cq0 = g_QS[qrow]   * (0.125f/16129.f);
    const float cq1 = g_QS[qrow+8] * (0.125f/16129.f);

    auto issue = [&](int kt){
        const int k0 = kt*64;
        const uint32_t d0 = sb + ((kt % 3)*A_STAGE)*4;
        {
            int key = tid >> 2, c4 = (tid & 3) << 2;
            cpa16(d0 + (key*20 + c4)*4,          KH_g + (size_t)(k0+key)*16 + c4);
            cpa16(d0 + (1280 + key*20 + c4)*4,   KL_g + (size_t)(k0+key)*16 + c4);
        }
        if (tid < 16)
            cpa16(d0 + (2560 + tid*4)*4, KS_g + k0 + tid*4);
        {
            int dr = tid >> 3, mc = (tid & 7) << 2;
            cpa16(d0 + (2624 + dr*36 + mc)*4,       Vh_g + (size_t)dr*(MM/2) + (k0>>1) + mc);
            cpa16(d0 + (2624 + (dr+32)*36 + mc)*4,  Vh_g + (size_t)(dr+32)*(MM/2) + (k0>>1) + mc);
            cpa16(d0 + (4928 + dr*36 + mc)*4,       Vl_g + (size_t)dr*(MM/2) + (k0>>1) + mc);
            cpa16(d0 + (4928 + (dr+32)*36 + mc)*4,  Vl_g + (size_t)(dr+32)*(MM/2) + (k0>>1) + mc);
        }
        CP_COMMIT();
    };

    float o[8][4];
    #pragma unroll
    for (int nt = 0; nt < 8; nt++)
        #pragma unroll
        for (int c = 0; c < 4; c++) o[nt][c] = 0.f;
    float m_run[2] = {-1e30f, -1e30f};
    float l_run[2] = {0.f, 0.f};

    const uint32_t lrow = (lane & 15), lcol = ((lane >> 4) << 2);
    const int ktEnd = 2*qt + 1;

    issue(0);
    issue(1);
    for (int kt = 0; kt <= ktEnd; kt++){
        const int k0 = kt*64;
        if (kt < ktEnd) CP_WAIT1(); else CP_WAIT0();
        __syncthreads();
        if (kt + 2 <= ktEnd) issue(kt + 2);

        const uint32_t st = sb + ((kt % 3)*A_STAGE)*4;
        const int stage_u32 = (kt % 3)*A_STAGE;

        int hh[8][4], xx[8][4];
        #pragma unroll
        for (int nt = 0; nt < 8; nt++)
            #pragma unroll
            for (int c = 0; c < 4; c++){ hh[nt][c] = 0; xx[nt][c] = 0; }

        #pragma unroll
        for (int ks = 0; ks < 2; ks++){
            const uint32_t fo = (lrow*20 + ks*8 + lcol)*4;
            #pragma unroll
            for (int ntp = 0; ntp < 4; ntp++){
                const uint32_t ra = st + ((ntp*16)*20)*4 + fo;
                uint32_t h0, h1, h2, h3, l0, l1, l2, l3;
                LDSM4(h0, h1, h2, h3, ra);
                LDSM4(l0, l1, l2, l3, ra + 1280*4);
                imma32(hh[2*ntp],   qH[ks], h0, h2);
                imma32(xx[2*ntp],   qH[ks], l0, l2);
                imma32(xx[2*ntp],   qL[ks], h0, h2);
                imma32(hh[2*ntp+1], qH[ks], h1, h3);
                imma32(xx[2*ntp+1], qH[ks], l1, l3);
                imma32(xx[2*ntp+1], qL[ks], h1, h3);
            }
        }

        const bool needMask = (kt >= 2*qt);
        float s[8][4];
        #pragma unroll
        for (int nt = 0; nt < 8; nt++){
            const int keyA = nt*8 + ((lane&3)<<1);
            const float skA = ((const float*)smu)[stage_u32 + 2560 + keyA];
            const float skB = ((const float*)smu)[stage_u32 + 2560 + keyA + 1];
            #pragma unroll
            for (int c = 0; c < 4; c++){
                const float rs = (c < 2) ? cq0 : cq1;
                const float sk = (c & 1) ? skB : skA;
                float v = rs * sk * ((float)hh[nt][c] + (float)xx[nt][c]*(1.f/128.f));
                if (needMask){
                    int rowL = wid*16 + (lane>>2) + ((c>>1)<<3);
                    int colL = keyA + (c&1);
                    if (k0 + colL > q0 + rowL) v = -1e30f;
                }
                s[nt][c] = v;
            }
        }

        #pragma unroll
        for (int hf = 0; hf < 2; hf++){
            float rm = -1e30f;
            #pragma unroll
            for (int nt = 0; nt < 8; nt++)
                rm = fmaxf(rm, fmaxf(s[nt][2*hf], s[nt][2*hf+1]));
            rm = fmaxf(rm, __shfl_xor_sync(0xffffffffu, rm, 1));
            rm = fmaxf(rm, __shfl_xor_sync(0xffffffffu, rm, 2));
            float mn  = fmaxf(m_run[hf], rm);
            float scl = __expf(m_run[hf] - mn);
            float psum = 0.f;
            #pragma unroll
            for (int nt = 0; nt < 8; nt++){
                float p0 = __expf(s[nt][2*hf]   - mn);
                float p1 = __expf(s[nt][2*hf+1] - mn);
                s[nt][2*hf] = p0; s[nt][2*hf+1] = p1;
                psum += p0 + p1;
            }
            psum += __shfl_xor_sync(0xffffffffu, psum, 1);
            psum += __shfl_xor_sync(0xffffffffu, psum, 2);
            l_run[hf] = l_run[hf]*scl + psum;
            m_run[hf] = mn;
            #pragma unroll
            for (int nt = 0; nt < 8; nt++){
                o[nt][2*hf]   *= scl;
                o[nt][2*hf+1] *= scl;
            }
        }

        #pragma unroll
        for (int kk = 0; kk < 4; kk++){
            uint32_t ah[4], al[4];
            float rx, ry;
            ah[0] = bsplit(s[2*kk][0],   s[2*kk][1],   rx, ry); al[0] = bpack(rx, ry);
            ah[1] = bsplit(s[2*kk][2],   s[2*kk][3],   rx, ry); al[1] = bpack(rx, ry);
            ah[2] = bsplit(s[2*kk+1][0], s[2*kk+1][1], rx, ry); al[2] = bpack(rx, ry);
            ah[3] = bsplit(s[2*kk+1][2], s[2*kk+1][3], rx, ry); al[3] = bpack(rx, ry);
            const uint32_t fo = (lrow*36 + kk*8 + lcol)*4;
            #pragma unroll
            for (int ntp = 0; ntp < 4; ntp++){
                const uint32_t rv = st + (2624 + (ntp*16)*36)*4 + fo;
                uint32_t h0, h1, h2, h3, l0, l1, l2, l3;
                LDSM4(h0, h1, h2, h3, rv);
                LDSM4(l0, l1, l2, l3, rv + 2304*4);
                mma16(o[2*ntp],   ah, h0, h2);
                mma16(o[2*ntp],   ah, l0, l2);
                mma16(o[2*ntp],   al, h0, h2);
                mma16(o[2*ntp+1], ah, h1, h3);
                mma16(o[2*ntp+1], ah, l1, l3);
                mma16(o[2*ntp+1], al, h1, h3);
            }
        }
    }

    const int b = bh >> 4, h = bh & 15;
    const float inv0 = 1.f / l_run[0], inv1 = 1.f / l_run[1];
    const int m0 = q0 + rA;
    #pragma unroll
    for (int nt = 0; nt < 8; nt++){
        int d0 = nt*8 + ((lane&3)<<1);
        *(float2*)&g_O[(size_t)(b*MM + m0)*DD + h*64 + d0] =
            make_float2(o[nt][0]*inv0, o[nt][1]*inv0);
        *(float2*)&g_O[(size_t)(b*MM + m0 + 8)*DD + h*64 + d0] =
            make_float2(o[nt][2]*inv1, o[nt][3]*inv1);
    }
}

// ---------------------------------------------------------------------------
extern "C" void kernel_launch(void* const* d_in, const int* in_sizes, int n_in,
                              void* d_out, int out_size)
{
    const float* x   = (const float*)d_in[0];
    const float* P_i = (const float*)d_in[1];
    const float* P_o = (const float*)d_in[2];
    float* y = (float*)d_out;

    uint32_t *xH, *xL, *piH, *piL, *poH, *poL, *oH, *oL;
    float *xS, *piS, *poS, *oS, *O;
    cudaGetSymbolAddress((void**)&xH,  g_xH);  cudaGetSymbolAddress((void**)&xL,  g_xL);
    cudaGetSymbolAddress((void**)&xS,  g_xS);
    cudaGetSymbolAddress((void**)&piH, g_PiH); cudaGetSymbolAddress((void**)&piL, g_PiL);
    cudaGetSymbolAddress((void**)&piS, g_PiS);
    cudaGetSymbolAddress((void**)&poH, g_PoH); cudaGetSymbolAddress((void**)&poL, g_PoL);
    cudaGetSymbolAddress((void**)&poS, g_PoS);
    cudaGetSymbolAddress((void**)&oH,  g_OH);  cudaGetSymbolAddress((void**)&oL,  g_OL);
    cudaGetSymbolAddress((void**)&oS,  g_OS);
    cudaGetSymbolAddress((void**)&O,   g_O);

    cudaFuncSetAttribute(gemm_i8<1>, cudaFuncAttributeMaxDynamicSharedMemorySize,
                         GI_SMEM_BYTES);
    cudaFuncSetAttribute(gemm_i8<2>, cudaFuncAttributeMaxDynamicSharedMemorySize,
                         GI_SMEM_BYTES);
    cudaFuncSetAttribute(attn_tc, cudaFuncAttributeMaxDynamicSharedMemorySize,
                         ATTN_SMEM_BYTES);

    // 0) quantize inputs
    quant_rows<<<BB*MM, 256>>>(x, xH, xL, xS);
    colmax<<<N3/256, 256>>>(P_i, piS, N3);
    colmax<<<DD/256, 256>>>(P_o, poS, DD);
    {
        dim3 g(N3/32, 1024/64);
        quant_wT<<<g, 256>>>(P_i, piH, piL, piS, N3);
    }
    {
        dim3 g(DD/32, 1024/64);
        quant_wT<<<g, 256>>>(P_o, poH, poL, poS, DD);
    }
    // 1) QKV projection (int8 Ozaki) with fused Q/K quant + V split epilogue
    {
        dim3 grid(N3/64, MM/128, BB);
        gemm_i8<1><<<grid, 256, GI_SMEM_BYTES>>>(xH, xL, piH, piL, xS, piS,
                                                 nullptr, MM, N3);
    }
    // 2) causal flash attention (int8 S, bf16 PV) -> fp32 O
    {
        dim3 grid(MM/128, BB*HH);
        attn_tc<<<grid, 256, ATTN_SMEM_BYTES>>>();
    }
    // 2.5) quantize O rows
    quant_rows<<<BB*MM, 256>>>(O, oH, oL, oS);
    // 3) output projection (int8 Ozaki)
    {
        dim3 grid(DD/64, (BB*MM)/128, 1);
        gemm_i8<2><<<grid, 256, GI_SMEM_BYTES>>>(oH, oL, poH, poL, oS, poS,
                                                 y, BB*MM, DD);
    }
}

// round 14
// speedup vs baseline: 1.1011x; 1.1011x over previous
#include <cuda_runtime.h>
#include <cuda_bf16.h>
#include <math.h>
#include <stdint.h>

#define BB 8
#define MM 1024
#define DD 1024
#define HH 16
#define KHD 64
#define N3 3072
#define KQ 256   // k-quads (4 int8) for K=1024

// fp32 intermediates
__device__ float g_Q[BB*HH*MM*KHD];
__device__ float g_K[BB*HH*MM*KHD];
__device__ float g_V[BB*HH*MM*KHD];
__device__ float g_O[BB*MM*DD];

// int8 Ozaki operands for projections: u32 = 4 consecutive-k int8
__device__ uint32_t g_xH [BB*MM*KQ],  g_xL [BB*MM*KQ];
__device__ float    g_xS [BB*MM];
__device__ uint32_t g_PiH[N3*KQ],     g_PiL[N3*KQ];
__device__ float    g_PiS[N3];
__device__ uint32_t g_PoH[DD*KQ],     g_PoL[DD*KQ];
__device__ float    g_PoS[DD];
__device__ uint32_t g_OH [BB*MM*KQ],  g_OL [BB*MM*KQ];
__device__ float    g_OS [BB*MM];

// int8 attention operands (rows of 64 -> 16 kq)
__device__ uint32_t g_QH[BB*HH*MM*16], g_QL[BB*HH*MM*16];
__device__ float    g_QS[BB*HH*MM];
__device__ uint32_t g_KH[BB*HH*MM*16], g_KL[BB*HH*MM*16];
__device__ float    g_KS[BB*HH*MM];

// bf16 V operands (packed bf16x2 key-pairs, transposed [bh][d][mp])
__device__ uint32_t g_Vph[BB*HH*KHD*(MM/2)], g_Vpl[BB*HH*KHD*(MM/2)];

// ---------------------------------------------------------------------------
__device__ __forceinline__ uint32_t bpack(float x, float y){
    __nv_bfloat162 h = __floats2bfloat162_rn(x, y);
    return *reinterpret_cast<uint32_t*>(&h);
}
__device__ __forceinline__ uint32_t bsplit(float x, float y, float& rx, float& ry){
    __nv_bfloat162 h = __floats2bfloat162_rn(x, y);
    rx = x - __low2float(h);
    ry = y - __high2float(h);
    return *reinterpret_cast<uint32_t*>(&h);
}
__device__ __forceinline__ void mma16(float* d, const uint32_t* a,
                                      uint32_t b0, uint32_t b1){
    asm volatile("mma.sync.aligned.m16n8k16.row.col.f32.bf16.bf16.f32 "
        "{%0,%1,%2,%3},{%4,%5,%6,%7},{%8,%9},{%0,%1,%2,%3};"
        : "+f"(d[0]), "+f"(d[1]), "+f"(d[2]), "+f"(d[3])
        : "r"(a[0]), "r"(a[1]), "r"(a[2]), "r"(a[3]), "r"(b0), "r"(b1));
}
__device__ __forceinline__ void imma32(int* d, const uint32_t* a,
                                       uint32_t b0, uint32_t b1){
    asm volatile("mma.sync.aligned.m16n8k32.row.col.s32.s8.s8.s32 "
        "{%0,%1,%2,%3},{%4,%5,%6,%7},{%8,%9},{%0,%1,%2,%3};"
        : "+r"(d[0]), "+r"(d[1]), "+r"(d[2]), "+r"(d[3])
        : "r"(a[0]), "r"(a[1]), "r"(a[2]), "r"(a[3]), "r"(b0), "r"(b1));
}
__device__ __forceinline__ uint32_t smem_u32(const void* p){
    uint32_t a;
    asm("{ .reg .u64 t; cvta.to.shared.u64 t, %1; cvt.u32.u64 %0, t; }"
        : "=r"(a) : "l"(p));
    return a;
}
__device__ __forceinline__ void cpa16(uint32_t dst, const void* src){
    asm volatile("cp.async.ca.shared.global [%0], [%1], 16;"
                 :: "r"(dst), "l"(src) : "memory");
}
#define CP_COMMIT() asm volatile("cp.async.commit_group;" ::: "memory")
#define CP_WAIT1()  asm volatile("cp.async.wait_group 1;" ::: "memory")
#define CP_WAIT0()  asm volatile("cp.async.wait_group 0;" ::: "memory")
#define LDSM4(r0,r1,r2,r3,addr) asm volatile( \
    "ldmatrix.sync.aligned.m8n8.x4.shared.b16 {%0,%1,%2,%3}, [%4];" \
    : "=r"(r0), "=r"(r1), "=r"(r2), "=r"(r3) : "r"(addr))

__device__ __forceinline__ uint32_t pack4(int a, int b, int c, int d){
    return (uint32_t)(uint8_t)(int8_t)a        | ((uint32_t)(uint8_t)(int8_t)b << 8)
         | ((uint32_t)(uint8_t)(int8_t)c << 16)| ((uint32_t)(uint8_t)(int8_t)d << 24);
}
__device__ __forceinline__ void q2(float f, float inv, int& h, int& l){
    float q = f * inv;
    h = __float2int_rn(q);
    l = __float2int_rn((q - (float)h) * 128.f);
}

// ---------------------------------------------------------------------------
// Quantization pre-passes
// ---------------------------------------------------------------------------
__global__ void quant_rows(const float* __restrict__ src,
                           uint32_t* __restrict__ H, uint32_t* __restrict__ L,
                           float* __restrict__ S){
    __shared__ float red[256];
    const int row = blockIdx.x, tid = threadIdx.x;
    float4 v = ((const float4*)(src + (size_t)row*1024))[tid];
    float m = fmaxf(fmaxf(fabsf(v.x), fabsf(v.y)), fmaxf(fabsf(v.z), fabsf(v.w)));
    red[tid] = m; __syncthreads();
    for (int o = 128; o > 0; o >>= 1){
        if (tid < o) red[tid] = fmaxf(red[tid], red[tid+o]);
        __syncthreads();
    }
    const float s = fmaxf(red[0], 1e-20f);
    const float inv = 127.f / s;
    int h0,l0,h1,l1,h2,l2,h3,l3;
    q2(v.x, inv, h0, l0); q2(v.y, inv, h1, l1);
    q2(v.z, inv, h2, l2); q2(v.w, inv, h3, l3);
    H[(size_t)row*KQ + tid] = pack4(h0,h1,h2,h3);
    L[(size_t)row*KQ + tid] = pack4(l0,l1,l2,l3);
    if (tid == 0) S[row] = s;
}
// coalesced column max: block = 32 columns x 8 k-lanes; k strided by 8.
// Same max-reduction values as before (order-independent) -> identical result.
__global__ void colmax2(const float* __restrict__ W, float* __restrict__ S, int N){
    __shared__ float red[8][33];
    const int tx = threadIdx.x, ty = threadIdx.y;
    const int n = blockIdx.x*32 + tx;
    float m = 0.f;
    for (int k = ty; k < 1024; k += 8)
        m = fmaxf(m, fabsf(W[(size_t)k*N + n]));
    red[ty][tx] = m;
    __syncthreads();
    if (ty == 0){
        #pragma unroll
        for (int j = 1; j < 8; j++) m = fmaxf(m, red[j][tx]);
        S[n] = fmaxf(m, 1e-20f);
    }
}
__global__ void quant_wT(const float* __restrict__ W,
                         uint32_t* __restrict__ H, uint32_t* __restrict__ L,
                         const float* __restrict__ S, int N){
    __shared__ float tile[64][33];
    const int n0 = blockIdx.x*32, k0 = blockIdx.y*64, tid = threadIdx.x;
    #pragma unroll
    for (int it = 0; it < 8; it++){
        int idx = tid + it*256;
        int kr = idx >> 5, nc = idx & 31;
        tile[kr][nc] = W[(size_t)(k0+kr)*N + n0 + nc];
    }
    __syncthreads();
    const int nl = tid >> 3, kq8 = tid & 7;
    const float inv = 127.f / S[n0 + nl];
    #pragma unroll
    for (int j = 0; j < 2; j++){
        int kq = kq8*2 + j;
        int h0,l0,h1,l1,h2,l2,h3,l3;
        q2(tile[kq*4+0][nl], inv, h0, l0);
        q2(tile[kq*4+1][nl], inv, h1, l1);
        q2(tile[kq*4+2][nl], inv, h2, l2);
        q2(tile[kq*4+3][nl], inv, h3, l3);
        H[(size_t)(n0+nl)*KQ + blockIdx.y*16 + kq] = pack4(h0,h1,h2,h3);
        L[(size_t)(n0+nl)*KQ + blockIdx.y*16 + kq] = pack4(l0,l1,l2,l3);
    }
}
// per-row-of-64 quantizer for Q/K: warp per row, 8 rows per block
__global__ void quant_qk64(const float* __restrict__ src,
                           uint32_t* __restrict__ H, uint32_t* __restrict__ L,
                           float* __restrict__ S){
    __shared__ float buf[8][64];
    __shared__ float sc[8];
    const int w = threadIdx.x >> 5, l = threadIdx.x & 31;
    const size_t row = (size_t)blockIdx.x*8 + w;
    float2 v = ((const float2*)(src + row*64))[l];
    buf[w][2*l]   = v.x;
    buf[w][2*l+1] = v.y;
    float m = fmaxf(fabsf(v.x), fabsf(v.y));
    #pragma unroll
    for (int o = 16; o > 0; o >>= 1)
        m = fmaxf(m, __shfl_xor_sync(0xffffffffu, m, o));
    if (l == 0){ float s = fmaxf(m, 1e-20f); sc[w] = s; S[row] = s; }
    __syncwarp();
    if (l < 16){
        const float inv = 127.f / sc[w];
        int h0,l0,h1,l1,h2,l2,h3,l3;
        q2(buf[w][4*l+0], inv, h0, l0);
        q2(buf[w][4*l+1], inv, h1, l1);
        q2(buf[w][4*l+2], inv, h2, l2);
        q2(buf[w][4*l+3], inv, h3, l3);
        H[row*16 + l] = pack4(h0,h1,h2,h3);
        L[row*16 + l] = pack4(l0,l1,l2,l3);
    }
}
// V: g_V [bh][m][64] fp32 -> [bh][d][mp] packed bf16 key-pairs
__global__ void split_vT(){
    __shared__ uint32_t sh[32][65], sl[32][65];
    const int bh = blockIdx.y, mp0 = blockIdx.x*32;
    const float* V = g_V + (size_t)bh*MM*KHD;
    const int tid = threadIdx.x;
    #pragma unroll
    for (int it = 0; it < 8; it++){
        int idx = tid + it*256;
        int mp = idx >> 6, d = idx & 63;
        float a = V[(size_t)(2*(mp0+mp))*KHD + d];
        float b = V[(size_t)(2*(mp0+mp)+1)*KHD + d];
        float rx, ry;
        sh[mp][d] = bsplit(a, b, rx, ry);
        sl[mp][d] = bpack(rx, ry);
    }
    __syncthreads();
    uint32_t* oh = g_Vph + (size_t)bh*KHD*(MM/2);
    uint32_t* ol = g_Vpl + (size_t)bh*KHD*(MM/2);
    #pragma unroll
    for (int it = 0; it < 8; it++){
        int idx = tid + it*256;
        int d = idx >> 5, mpi = idx & 31;
        oh[(size_t)d*(MM/2) + mp0 + mpi] = sh[mpi][d];
        ol[(size_t)d*(MM/2) + mp0 + mpi] = sl[mpi][d];
    }
}

// ---------------------------------------------------------------------------
// int8 Ozaki GEMM (R12). MODE 1: QKV -> fp32 g_Q/g_K/g_V. MODE 2: proj.
// ---------------------------------------------------------------------------
#define GI_STAGE 7680
#define GI_SMEM_BYTES (2*GI_STAGE*4)

template<int MODE>
__global__ __launch_bounds__(256, 2) void gemm_i8(
    const uint32_t* __restrict__ AH, const uint32_t* __restrict__ AL,
    const uint32_t* __restrict__ BH, const uint32_t* __restrict__ BL,
    const float* __restrict__ SA, const float* __restrict__ SB,
    float* __restrict__ C, int Mx, int Nx)
{
    extern __shared__ uint32_t smg[];
    const uint32_t sb = smem_u32(smg);
    const int tid = threadIdx.x, lane = tid & 31, wid = tid >> 5;
    const int wm = wid >> 2, wn = wid & 3;
    const int bm = blockIdx.y, bn = blockIdx.x, bz = blockIdx.z;

    const uint32_t* Ah = AH + (size_t)bz * Mx * KQ;
    const uint32_t* Al = AL + (size_t)bz * Mx * KQ;

    auto issue = [&](int t){
        const int kq0 = t << 4;
        const uint32_t d0 = sb + ((t & 1)*GI_STAGE)*4;
        #pragma unroll
        for (int it = 0; it < 2; it++){
            int idx = tid + it*256;
            int ra = idx >> 2, ca = (idx & 3) << 2;
            cpa16(d0 + (ra*20 + ca)*4,          Ah + (size_t)(bm*128 + ra)*KQ + kq0 + ca);
            cpa16(d0 + (2560 + ra*20 + ca)*4,   Al + (size_t)(bm*128 + ra)*KQ + kq0 + ca);
        }
        {
            int rb = tid >> 2, cb = (tid & 3) << 2;
            cpa16(d0 + (5120 + rb*20 + cb)*4,   BH + (size_t)(bn*64 + rb)*KQ + kq0 + cb);
            cpa16(d0 + (6400 + rb*20 + cb)*4,   BL + (size_t)(bn*64 + rb)*KQ + kq0 + cb);
        }
        CP_COMMIT();
    };

    int hh[4][2][4], xx[4][2][4];
    #pragma unroll
    for (int mt = 0; mt < 4; mt++)
        #pragma unroll
        for (int nt = 0; nt < 2; nt++)
            #pragma unroll
            for (int c = 0; c < 4; c++){ hh[mt][nt][c] = 0; xx[mt][nt][c] = 0; }

    const uint32_t lrow = (lane & 15), lcolo = ((lane >> 4) << 2);
    const int nT = 16;

    issue(0);
    for (int t = 0; t < nT; ++t){
        CP_WAIT0();
        __syncthreads();
        if (t + 1 < nT) issue(t + 1);

        const uint32_t st = sb + ((t & 1)*GI_STAGE)*4;
        #pragma unroll
        for (int kk = 0; kk < 2; kk++){
            const uint32_t fo = (lrow*20 + kk*8 + lcolo)*4;
            uint32_t aH_[4][4], aL_[4][4];
            #pragma unroll
            for (int mt = 0; mt < 4; mt++){
                const uint32_t ra = st + ((wm*64 + mt*16)*20)*4 + fo;
                LDSM4(aH_[mt][0], aH_[mt][1], aH_[mt][2], aH_[mt][3], ra);
                LDSM4(aL_[mt][0], aL_[mt][1], aL_[mt][2], aL_[mt][3], ra + 2560*4);
            }
            const uint32_t rb = st + (5120 + (wn*16)*20)*4 + fo;
            uint32_t bH0, bH1, bH2, bH3, bL0, bL1, bL2, bL3;
            LDSM4(bH0, bH1, bH2, bH3, rb);
            LDSM4(bL0, bL1, bL2, bL3, rb + 1280*4);
            #pragma unroll
            for (int mt = 0; mt < 4; mt++){
                imma32(hh[mt][0], aH_[mt], bH0, bH2);
                imma32(xx[mt][0], aH_[mt], bL0, bL2);
                imma32(xx[mt][0], aL_[mt], bH0, bH2);
                imma32(hh[mt][1], aH_[mt], bH1, bH3);
                imma32(xx[mt][1], aH_[mt], bL1, bL3);
                imma32(xx[mt][1], aL_[mt], bH1, bH3);
            }
        }
    }

    #pragma unroll
    for (int mt = 0; mt < 4; mt++)
        #pragma unroll
        for (int nt = 0; nt < 2; nt++){
            const int col0 = bn*64 + wn*16 + nt*8 + ((lane&3)<<1);
            const float t0 = SB[col0], t1 = SB[col0+1];
            #pragma unroll
            for (int half = 0; half < 2; half++){
                const int row = bm*128 + wm*64 + mt*16 + (lane>>2) + half*8;
                const float s = SA[(size_t)bz*Mx + row];
                const float c0 = s*t0*(1.f/16129.f), c1 = s*t1*(1.f/16129.f);
                const float v0 = c0*((float)hh[mt][nt][2*half]   + (float)xx[mt][nt][2*half]  *(1.f/128.f));
                const float v1 = c1*((float)hh[mt][nt][2*half+1] + (float)xx[mt][nt][2*half+1]*(1.f/128.f));
                if (MODE == 1){
                    const int h = col0 / 192;
                    const int rr = col0 - 192*h;
                    const size_t mi = (size_t)((bz*HH + h)*MM + row);
                    if (rr < 64)
                        *(float2*)&g_Q[mi*KHD + rr]       = make_float2(v0, v1);
                    else if (rr < 128)
                        *(float2*)&g_K[mi*KHD + rr - 64]  = make_float2(v0, v1);
                    else
                        *(float2*)&g_V[mi*KHD + rr - 128] = make_float2(v0, v1);
                } else {
                    *(float2*)&C[(size_t)row*Nx + col0] = make_float2(v0, v1);
                }
            }
        }
}

// ---------------------------------------------------------------------------
// Flash attention: S = QK^T int8 Ozaki, softmax fp32, P.V bf16 3x (R12).
// ---------------------------------------------------------------------------
#define A_STAGE 7232
#define ATTN_SMEM_BYTES (3*A_STAGE*4)

__global__ __launch_bounds__(256, 2) void attn_tc()
{
    extern __shared__ uint32_t smu[];
    const uint32_t sb = smem_u32(smu);

    const int tid = threadIdx.x, lane = tid & 31, wid = tid >> 5;
    const int qt = gridDim.x - 1 - blockIdx.x;
    const int bh = blockIdx.y;
    const int q0 = qt * 128;

    const uint32_t* KH_g = g_KH + (size_t)bh*MM*16;
    const uint32_t* KL_g = g_KL + (size_t)bh*MM*16;
    const float*    KS_g = g_KS + (size_t)bh*MM;
    const uint32_t* Vh_g = g_Vph + (size_t)bh*KHD*(MM/2);
    const uint32_t* Vl_g = g_Vpl + (size_t)bh*KHD*(MM/2);

    const int rA = wid*16 + (lane>>2);
    const size_t qrow = (size_t)bh*MM + q0 + rA;

    uint32_t qH[2][4], qL[2][4];
    #pragma unroll
    for (int ks = 0; ks < 2; ks++){
        int kq = ks*8 + (lane & 3);
        qH[ks][0] = g_QH[qrow*16 + kq];
        qH[ks][1] = g_QH[(qrow+8)*16 + kq];
        qH[ks][2] = g_QH[qrow*16 + kq + 4];
        qH[ks][3] = g_QH[(qrow+8)*16 + kq + 4];
        qL[ks][0] = g_QL[qrow*16 + kq];
        qL[ks][1] = g_QL[(qrow+8)*16 + kq];
        qL[ks][2] = g_QL[qrow*16 + kq + 4];
        qL[ks][3] = g_QL[(qrow+8)*16 + kq + 4];
    }
    const float cq0 = g_QS[qrow]   * (0.125f/16129.f);
    const float cq1 = g_QS[qrow+8] * (0.125f/16129.f);

    auto issue = [&](int kt){
        const int k0 = kt*64;
        const uint32_t d0 = sb + ((kt % 3)*A_STAGE)*4;
        {
            int key = tid >> 2, c4 = (tid & 3) << 2;
            cpa16(d0 + (key*20 + c4)*4,          KH_g + (size_t)(k0+key)*16 + c4);
            cpa16(d0 + (1280 + key*20 + c4)*4,   KL_g + (size_t)(k0+key)*16 + c4);
        }
        if (tid < 16)
            cpa16(d0 + (2560 + tid*4)*4, KS_g + k0 + tid*4);
        {
            int dr = tid >> 3, mc = (tid & 7) << 2;
            cpa16(d0 + (2624 + dr*36 + mc)*4,       Vh_g + (size_t)dr*(MM/2) + (k0>>1) + mc);
            cpa16(d0 + (2624 + (dr+32)*36 + mc)*4,  Vh_g + (size_t)(dr+32)*(MM/2) + (k0>>1) + mc);
            cpa16(d0 + (4928 + dr*36 + mc)*4,       Vl_g + (size_t)dr*(MM/2) + (k0>>1) + mc);
            cpa16(d0 + (4928 + (dr+32)*36 + mc)*4,  Vl_g + (size_t)(dr+32)*(MM/2) + (k0>>1) + mc);
        }
        CP_COMMIT();
    };

    float o[8][4];
    #pragma unroll
    for (int nt = 0; nt < 8; nt++)
        #pragma unroll
        for (int c = 0; c < 4; c++) o[nt][c] = 0.f;
    float m_run[2] = {-1e30f, -1e30f};
    float l_run[2] = {0.f, 0.f};

    const uint32_t lrow = (lane & 15), lcol = ((lane >> 4) << 2);
    const int ktEnd = 2*qt + 1;

    issue(0);
    issue(1);
    for (int kt = 0; kt <= ktEnd; kt++){
        const int k0 = kt*64;
        if (kt < ktEnd) CP_WAIT1(); else CP_WAIT0();
        __syncthreads();
        if (kt + 2 <= ktEnd) issue(kt + 2);

        const uint32_t st = sb + ((kt % 3)*A_STAGE)*4;
        const int stage_u32 = (kt % 3)*A_STAGE;

        int hh[8][4], xx[8][4];
        #pragma unroll
        for (int nt = 0; nt < 8; nt++)
            #pragma unroll
            for (int c = 0; c < 4; c++){ hh[nt][c] = 0; xx[nt][c] = 0; }

        #pragma unroll
        for (int ks = 0; ks < 2; ks++){
            const uint32_t fo = (lrow*20 + ks*8 + lcol)*4;
            #pragma unroll
            for (int ntp = 0; ntp < 4; ntp++){
                const uint32_t ra = st + ((ntp*16)*20)*4 + fo;
                uint32_t h0, h1, h2, h3, l0, l1, l2, l3;
                LDSM4(h0, h1, h2, h3, ra);
                LDSM4(l0, l1, l2, l3, ra + 1280*4);
                imma32(hh[2*ntp],   qH[ks], h0, h2);
                imma32(xx[2*ntp],   qH[ks], l0, l2);
                imma32(xx[2*ntp],   qL[ks], h0, h2);
                imma32(hh[2*ntp+1], qH[ks], h1, h3);
                imma32(xx[2*ntp+1], qH[ks], l1, l3);
                imma32(xx[2*ntp+1], qL[ks], h1, h3);
            }
        }

        const bool needMask = (kt >= 2*qt);
        float s[8][4];
        #pragma unroll
        for (int nt = 0; nt < 8; nt++){
            const int keyA = nt*8 + ((lane&3)<<1);
            const float skA = ((const float*)smu)[stage_u32 + 2560 + keyA];
            const float skB = ((const float*)smu)[stage_u32 + 2560 + keyA + 1];
            #pragma unroll
            for (int c = 0; c < 4; c++){
                const float rs = (c < 2) ? cq0 : cq1;
                const float sk = (c & 1) ? skB : skA;
                float v = rs * sk * ((float)hh[nt][c] + (float)xx[nt][c]*(1.f/128.f));
                if (needMask){
                    int rowL = wid*16 + (lane>>2) + ((c>>1)<<3);
                    int colL = keyA + (c&1);
                    if (k0 + colL > q0 + rowL) v = -1e30f;
                }
                s[nt][c] = v;
            }
        }

        #pragma unroll
        for (int hf = 0; hf < 2; hf++){
            float rm = -1e30f;
            #pragma unroll
            for (int nt = 0; nt < 8; nt++)
                rm = fmaxf(rm, fmaxf(s[nt][2*hf], s[nt][2*hf+1]));
            rm = fmaxf(rm, __shfl_xor_sync(0xffffffffu, rm, 1));
            rm = fmaxf(rm, __shfl_xor_sync(0xffffffffu, rm, 2));
            float mn  = fmaxf(m_run[hf], rm);
            float scl = __expf(m_run[hf] - mn);
            float psum = 0.f;
            #pragma unroll
            for (int nt = 0; nt < 8; nt++){
                float p0 = __expf(s[nt][2*hf]   - mn);
                float p1 = __expf(s[nt][2*hf+1] - mn);
                s[nt][2*hf] = p0; s[nt][2*hf+1] = p1;
                psum += p0 + p1;
            }
            psum += __shfl_xor_sync(0xffffffffu, psum, 1);
            psum += __shfl_xor_sync(0xffffffffu, psum, 2);
            l_run[hf] = l_run[hf]*scl + psum;
            m_run[hf] = mn;
            #pragma unroll
            for (int nt = 0; nt < 8; nt++){
                o[nt][2*hf]   *= scl;
                o[nt][2*hf+1] *= scl;
            }
        }

        #pragma unroll
        for (int kk = 0; kk < 4; kk++){
            uint32_t ah[4], al[4];
            float rx, ry;
            ah[0] = bsplit(s[2*kk][0],   s[2*kk][1],   rx, ry); al[0] = bpack(rx, ry);
            ah[1] = bsplit(s[2*kk][2],   s[2*kk][3],   rx, ry); al[1] = bpack(rx, ry);
            ah[2] = bsplit(s[2*kk+1][0], s[2*kk+1][1], rx, ry); al[2] = bpack(rx, ry);
            ah[3] = bsplit(s[2*kk+1][2], s[2*kk+1][3], rx, ry); al[3] = bpack(rx, ry);
            const uint32_t fo = (lrow*36 + kk*8 + lcol)*4;
            #pragma unroll
            for (int ntp = 0; ntp < 4; ntp++){
                const uint32_t rv = st + (2624 + (ntp*16)*36)*4 + fo;
                uint32_t h0, h1, h2, h3, l0, l1, l2, l3;
                LDSM4(h0, h1, h2, h3, rv);
                LDSM4(l0, l1, l2, l3, rv + 2304*4);
                mma16(o[2*ntp],   ah, h0, h2);
                mma16(o[2*ntp],   ah, l0, l2);
                mma16(o[2*ntp],   al, h0, h2);
                mma16(o[2*ntp+1], ah, h1, h3);
                mma16(o[2*ntp+1], ah, l1, l3);
                mma16(o[2*ntp+1], al, h1, h3);
            }
        }
    }

    const int b = bh >> 4, h = bh & 15;
    const float inv0 = 1.f / l_run[0], inv1 = 1.f / l_run[1];
    const int m0 = q0 + rA;
    #pragma unroll
    for (int nt = 0; nt < 8; nt++){
        int d0 = nt*8 + ((lane&3)<<1);
        *(float2*)&g_O[(size_t)(b*MM + m0)*DD + h*64 + d0] =
            make_float2(o[nt][0]*inv0, o[nt][1]*inv0);
        *(float2*)&g_O[(size_t)(b*MM + m0 + 8)*DD + h*64 + d0] =
            make_float2(o[nt][2]*inv1, o[nt][3]*inv1);
    }
}

// ---------------------------------------------------------------------------
extern "C" void kernel_launch(void* const* d_in, const int* in_sizes, int n_in,
                              void* d_out, int out_size)
{
    const float* x   = (const float*)d_in[0];
    const float* P_i = (const float*)d_in[1];
    const float* P_o = (const float*)d_in[2];
    float* y = (float*)d_out;

    uint32_t *xH, *xL, *piH, *piL, *poH, *poL, *oH, *oL, *qH, *qL, *kH, *kL;
    float *xS, *piS, *poS, *oS, *qS, *kS, *Q, *K, *O;
    cudaGetSymbolAddress((void**)&xH,  g_xH);  cudaGetSymbolAddress((void**)&xL,  g_xL);
    cudaGetSymbolAddress((void**)&xS,  g_xS);
    cudaGetSymbolAddress((void**)&piH, g_PiH); cudaGetSymbolAddress((void**)&piL, g_PiL);
    cudaGetSymbolAddress((void**)&piS, g_PiS);
    cudaGetSymbolAddress((void**)&poH, g_PoH); cudaGetSymbolAddress((void**)&poL, g_PoL);
    cudaGetSymbolAddress((void**)&poS, g_PoS);
    cudaGetSymbolAddress((void**)&oH,  g_OH);  cudaGetSymbolAddress((void**)&oL,  g_OL);
    cudaGetSymbolAddress((void**)&oS,  g_OS);
    cudaGetSymbolAddress((void**)&qH,  g_QH);  cudaGetSymbolAddress((void**)&qL,  g_QL);
    cudaGetSymbolAddress((void**)&qS,  g_QS);
    cudaGetSymbolAddress((void**)&kH,  g_KH);  cudaGetSymbolAddress((void**)&kL,  g_KL);
    cudaGetSymbolAddress((void**)&kS,  g_KS);
    cudaGetSymbolAddress((void**)&Q,   g_Q);
    cudaGetSymbolAddress((void**)&K,   g_K);
    cudaGetSymbolAddress((void**)&O,   g_O);

    cudaFuncSetAttribute(gemm_i8<1>, cudaFuncAttributeMaxDynamicSharedMemorySize,
                         GI_SMEM_BYTES);
    cudaFuncSetAttribute(gemm_i8<2>, cudaFuncAttributeMaxDynamicSharedMemorySize,
                         GI_SMEM_BYTES);
    cudaFuncSetAttribute(attn_tc, cudaFuncAttributeMaxDynamicSharedMemorySize,
                         ATTN_SMEM_BYTES);

    // 0) quantize inputs (colmax2: coalesced column-max)
    quant_rows<<<BB*MM, 256>>>(x, xH, xL, xS);
    {
        dim3 b(32, 8);
        colmax2<<<N3/32, b>>>(P_i, piS, N3);
        colmax2<<<DD/32, b>>>(P_o, poS, DD);
    }
    {
        dim3 g(N3/32, 1024/64);
        quant_wT<<<g, 256>>>(P_i, piH, piL, piS, N3);
    }
    {
        dim3 g(DD/32, 1024/64);
        quant_wT<<<g, 256>>>(P_o, poH, poL, poS, DD);
    }
    // 1) QKV projection (int8 Ozaki) -> fp32 Q/K/V
    {
        dim3 grid(N3/64, MM/128, BB);
        gemm_i8<1><<<grid, 256, GI_SMEM_BYTES>>>(xH, xL, piH, piL, xS, piS,
                                                 nullptr, MM, N3);
    }
    // 1.5) quantize Q/K rows (int8 pairs), split V to bf16 pairs
    quant_qk64<<<(BB*HH*MM)/8, 256>>>(Q, qH, qL, qS);
    quant_qk64<<<(BB*HH*MM)/8, 256>>>(K, kH, kL, kS);
    {
        dim3 g(MM/64, BB*HH);
        split_vT<<<g, 256>>>();
    }
    // 2) causal flash attention (int8 S, bf16 PV) -> fp32 O
    {
        dim3 grid(MM/128, BB*HH);
        attn_tc<<<grid, 256, ATTN_SMEM_BYTES>>>();
    }
    // 2.5) quantize O rows
    quant_rows<<<BB*MM, 256>>>(O, oH, oL, oS);
    // 3) output projection (int8 Ozaki)
    {
        dim3 grid(DD/64, (BB*MM)/128, 1);
        gemm_i8<2><<<grid, 256, GI_SMEM_BYTES>>>(oH, oL, poH, poL, oS, poS,
                                                 y, BB*MM, DD);
    }
}

// round 15
// speedup vs baseline: 1.1183x; 1.0156x over previous
#include <cuda_runtime.h>
#include <cuda_bf16.h>
#include <math.h>
#include <stdint.h>

#define BB 8
#define MM 1024
#define DD 1024
#define HH 16
#define KHD 64
#define N3 3072
#define KQ 256   // k-quads (4 int8) for K=1024

// fp32 intermediates
__device__ float g_Q[BB*HH*MM*KHD];
__device__ float g_K[BB*HH*MM*KHD];
__device__ float g_V[BB*HH*MM*KHD];
__device__ float g_O[BB*MM*DD];

// int8 Ozaki operands for projections: u32 = 4 consecutive-k int8
__device__ uint32_t g_xH [BB*MM*KQ],  g_xL [BB*MM*KQ];
__device__ float    g_xS [BB*MM];
__device__ uint32_t g_PiH[N3*KQ],     g_PiL[N3*KQ];
__device__ float    g_PiS[N3];
__device__ uint32_t g_PoH[DD*KQ],     g_PoL[DD*KQ];
__device__ float    g_PoS[DD];
__device__ uint32_t g_OH [BB*MM*KQ],  g_OL [BB*MM*KQ];
__device__ float    g_OS [BB*MM];

// int8 attention operands (rows of 64 -> 16 kq)
__device__ uint32_t g_QH[BB*HH*MM*16], g_QL[BB*HH*MM*16];
__device__ float    g_QS[BB*HH*MM];
__device__ uint32_t g_KH[BB*HH*MM*16], g_KL[BB*HH*MM*16];
__device__ float    g_KS[BB*HH*MM];

// bf16 V operands (packed bf16x2 key-pairs, transposed [bh][d][mp])
__device__ uint32_t g_Vph[BB*HH*KHD*(MM/2)], g_Vpl[BB*HH*KHD*(MM/2)];

// ---------------------------------------------------------------------------
__device__ __forceinline__ uint32_t bpack(float x, float y){
    __nv_bfloat162 h = __floats2bfloat162_rn(x, y);
    return *reinterpret_cast<uint32_t*>(&h);
}
__device__ __forceinline__ uint32_t bsplit(float x, float y, float& rx, float& ry){
    __nv_bfloat162 h = __floats2bfloat162_rn(x, y);
    rx = x - __low2float(h);
    ry = y - __high2float(h);
    return *reinterpret_cast<uint32_t*>(&h);
}
__device__ __forceinline__ void mma16(float* d, const uint32_t* a,
                                      uint32_t b0, uint32_t b1){
    asm volatile("mma.sync.aligned.m16n8k16.row.col.f32.bf16.bf16.f32 "
        "{%0,%1,%2,%3},{%4,%5,%6,%7},{%8,%9},{%0,%1,%2,%3};"
        : "+f"(d[0]), "+f"(d[1]), "+f"(d[2]), "+f"(d[3])
        : "r"(a[0]), "r"(a[1]), "r"(a[2]), "r"(a[3]), "r"(b0), "r"(b1));
}
__device__ __forceinline__ void imma32(int* d, const uint32_t* a,
                                       uint32_t b0, uint32_t b1){
    asm volatile("mma.sync.aligned.m16n8k32.row.col.s32.s8.s8.s32 "
        "{%0,%1,%2,%3},{%4,%5,%6,%7},{%8,%9},{%0,%1,%2,%3};"
        : "+r"(d[0]), "+r"(d[1]), "+r"(d[2]), "+r"(d[3])
        : "r"(a[0]), "r"(a[1]), "r"(a[2]), "r"(a[3]), "r"(b0), "r"(b1));
}
__device__ __forceinline__ uint32_t smem_u32(const void* p){
    uint32_t a;
    asm("{ .reg .u64 t; cvta.to.shared.u64 t, %1; cvt.u32.u64 %0, t; }"
        : "=r"(a) : "l"(p));
    return a;
}
__device__ __forceinline__ void cpa16(uint32_t dst, const void* src){
    asm volatile("cp.async.ca.shared.global [%0], [%1], 16;"
                 :: "r"(dst), "l"(src) : "memory");
}
#define CP_COMMIT() asm volatile("cp.async.commit_group;" ::: "memory")
#define CP_WAIT1()  asm volatile("cp.async.wait_group 1;" ::: "memory")
#define CP_WAIT0()  asm volatile("cp.async.wait_group 0;" ::: "memory")
#define LDSM4(r0,r1,r2,r3,addr) asm volatile( \
    "ldmatrix.sync.aligned.m8n8.x4.shared.b16 {%0,%1,%2,%3}, [%4];" \
    : "=r"(r0), "=r"(r1), "=r"(r2), "=r"(r3) : "r"(addr))

__device__ __forceinline__ uint32_t pack4(int a, int b, int c, int d){
    return (uint32_t)(uint8_t)(int8_t)a        | ((uint32_t)(uint8_t)(int8_t)b << 8)
         | ((uint32_t)(uint8_t)(int8_t)c << 16)| ((uint32_t)(uint8_t)(int8_t)d << 24);
}
__device__ __forceinline__ void q2(float f, float inv, int& h, int& l){
    float q = f * inv;
    h = __float2int_rn(q);
    l = __float2int_rn((q - (float)h) * 128.f);
}

// ---------------------------------------------------------------------------
// Quantization pre-passes
// ---------------------------------------------------------------------------
__global__ void quant_rows(const float* __restrict__ src,
                           uint32_t* __restrict__ H, uint32_t* __restrict__ L,
                           float* __restrict__ S){
    __shared__ float red[256];
    const int row = blockIdx.x, tid = threadIdx.x;
    float4 v = ((const float4*)(src + (size_t)row*1024))[tid];
    float m = fmaxf(fmaxf(fabsf(v.x), fabsf(v.y)), fmaxf(fabsf(v.z), fabsf(v.w)));
    red[tid] = m; __syncthreads();
    for (int o = 128; o > 0; o >>= 1){
        if (tid < o) red[tid] = fmaxf(red[tid], red[tid+o]);
        __syncthreads();
    }
    const float s = fmaxf(red[0], 1e-20f);
    const float inv = 127.f / s;
    int h0,l0,h1,l1,h2,l2,h3,l3;
    q2(v.x, inv, h0, l0); q2(v.y, inv, h1, l1);
    q2(v.z, inv, h2, l2); q2(v.w, inv, h3, l3);
    H[(size_t)row*KQ + tid] = pack4(h0,h1,h2,h3);
    L[(size_t)row*KQ + tid] = pack4(l0,l1,l2,l3);
    if (tid == 0) S[row] = s;
}
// coalesced column max: block = 32 columns x 8 k-lanes
__global__ void colmax2(const float* __restrict__ W, float* __restrict__ S, int N){
    __shared__ float red[8][33];
    const int tx = threadIdx.x, ty = threadIdx.y;
    const int n = blockIdx.x*32 + tx;
    float m = 0.f;
    for (int k = ty; k < 1024; k += 8)
        m = fmaxf(m, fabsf(W[(size_t)k*N + n]));
    red[ty][tx] = m;
    __syncthreads();
    if (ty == 0){
        #pragma unroll
        for (int j = 1; j < 8; j++) m = fmaxf(m, red[j][tx]);
        S[n] = fmaxf(m, 1e-20f);
    }
}
__global__ void quant_wT(const float* __restrict__ W,
                         uint32_t* __restrict__ H, uint32_t* __restrict__ L,
                         const float* __restrict__ S, int N){
    __shared__ float tile[64][33];
    const int n0 = blockIdx.x*32, k0 = blockIdx.y*64, tid = threadIdx.x;
    #pragma unroll
    for (int it = 0; it < 8; it++){
        int idx = tid + it*256;
        int kr = idx >> 5, nc = idx & 31;
        tile[kr][nc] = W[(size_t)(k0+kr)*N + n0 + nc];
    }
    __syncthreads();
    const int nl = tid >> 3, kq8 = tid & 7;
    const float inv = 127.f / S[n0 + nl];
    #pragma unroll
    for (int j = 0; j < 2; j++){
        int kq = kq8*2 + j;
        int h0,l0,h1,l1,h2,l2,h3,l3;
        q2(tile[kq*4+0][nl], inv, h0, l0);
        q2(tile[kq*4+1][nl], inv, h1, l1);
        q2(tile[kq*4+2][nl], inv, h2, l2);
        q2(tile[kq*4+3][nl], inv, h3, l3);
        H[(size_t)(n0+nl)*KQ + blockIdx.y*16 + kq] = pack4(h0,h1,h2,h3);
        L[(size_t)(n0+nl)*KQ + blockIdx.y*16 + kq] = pack4(l0,l1,l2,l3);
    }
}
// per-row-of-64 quantizer for Q/K: warp per row, 8 rows per block
__global__ void quant_qk64(const float* __restrict__ src,
                           uint32_t* __restrict__ H, uint32_t* __restrict__ L,
                           float* __restrict__ S){
    __shared__ float buf[8][64];
    __shared__ float sc[8];
    const int w = threadIdx.x >> 5, l = threadIdx.x & 31;
    const size_t row = (size_t)blockIdx.x*8 + w;
    float2 v = ((const float2*)(src + row*64))[l];
    buf[w][2*l]   = v.x;
    buf[w][2*l+1] = v.y;
    float m = fmaxf(fabsf(v.x), fabsf(v.y));
    #pragma unroll
    for (int o = 16; o > 0; o >>= 1)
        m = fmaxf(m, __shfl_xor_sync(0xffffffffu, m, o));
    if (l == 0){ float s = fmaxf(m, 1e-20f); sc[w] = s; S[row] = s; }
    __syncwarp();
    if (l < 16){
        const float inv = 127.f / sc[w];
        int h0,l0,h1,l1,h2,l2,h3,l3;
        q2(buf[w][4*l+0], inv, h0, l0);
        q2(buf[w][4*l+1], inv, h1, l1);
        q2(buf[w][4*l+2], inv, h2, l2);
        q2(buf[w][4*l+3], inv, h3, l3);
        H[row*16 + l] = pack4(h0,h1,h2,h3);
        L[row*16 + l] = pack4(l0,l1,l2,l3);
    }
}
// V: g_V [bh][m][64] fp32 -> [bh][d][mp] packed bf16 key-pairs
__global__ void split_vT(){
    __shared__ uint32_t sh[32][65], sl[32][65];
    const int bh = blockIdx.y, mp0 = blockIdx.x*32;
    const float* V = g_V + (size_t)bh*MM*KHD;
    const int tid = threadIdx.x;
    #pragma unroll
    for (int it = 0; it < 8; it++){
        int idx = tid + it*256;
        int mp = idx >> 6, d = idx & 63;
        float a = V[(size_t)(2*(mp0+mp))*KHD + d];
        float b = V[(size_t)(2*(mp0+mp)+1)*KHD + d];
        float rx, ry;
        sh[mp][d] = bsplit(a, b, rx, ry);
        sl[mp][d] = bpack(rx, ry);
    }
    __syncthreads();
    uint32_t* oh = g_Vph + (size_t)bh*KHD*(MM/2);
    uint32_t* ol = g_Vpl + (size_t)bh*KHD*(MM/2);
    #pragma unroll
    for (int it = 0; it < 8; it++){
        int idx = tid + it*256;
        int d = idx >> 5, mpi = idx & 31;
        oh[(size_t)d*(MM/2) + mp0 + mpi] = sh[mpi][d];
        ol[(size_t)d*(MM/2) + mp0 + mpi] = sl[mpi][d];
    }
}

// ---------------------------------------------------------------------------
// int8 Ozaki GEMM: CTA 128m x 64n, k-tile 64 (16 kq), 8 warps as 4m x 2n
// (warp tile 32m x 32n: mt=2, nt=4). Balanced operand duplication:
// per k-tile smem reads 64 KB (vs 80 KB at 2m x 4n) for the same 384 IMMA.
// 2-stage cp.async ring, one barrier per tile. smem per stage (u32):
// AH[128][20] @0 | AL @2560 | BH[64][20] @5120 | BL @6400 = 7680.
// MODE 1: QKV -> fp32 g_Q/g_K/g_V. MODE 2: proj -> C.
// ---------------------------------------------------------------------------
#define GI_STAGE 7680
#define GI_SMEM_BYTES (2*GI_STAGE*4)

template<int MODE>
__global__ __launch_bounds__(256, 2) void gemm_i8(
    const uint32_t* __restrict__ AH, const uint32_t* __restrict__ AL,
    const uint32_t* __restrict__ BH, const uint32_t* __restrict__ BL,
    const float* __restrict__ SA, const float* __restrict__ SB,
    float* __restrict__ C, int Mx, int Nx)
{
    extern __shared__ uint32_t smg[];
    const uint32_t sb = smem_u32(smg);
    const int tid = threadIdx.x, lane = tid & 31, wid = tid >> 5;
    const int wm = wid >> 1, wn = wid & 1;     // 4m x 2n warp grid
    const int bm = blockIdx.y, bn = blockIdx.x, bz = blockIdx.z;

    const uint32_t* Ah = AH + (size_t)bz * Mx * KQ;
    const uint32_t* Al = AL + (size_t)bz * Mx * KQ;

    auto issue = [&](int t){
        const int kq0 = t << 4;
        const uint32_t d0 = sb + ((t & 1)*GI_STAGE)*4;
        #pragma unroll
        for (int it = 0; it < 2; it++){
            int idx = tid + it*256;
            int ra = idx >> 2, ca = (idx & 3) << 2;
            cpa16(d0 + (ra*20 + ca)*4,          Ah + (size_t)(bm*128 + ra)*KQ + kq0 + ca);
            cpa16(d0 + (2560 + ra*20 + ca)*4,   Al + (size_t)(bm*128 + ra)*KQ + kq0 + ca);
        }
        {
            int rb = tid >> 2, cb = (tid & 3) << 2;
            cpa16(d0 + (5120 + rb*20 + cb)*4,   BH + (size_t)(bn*64 + rb)*KQ + kq0 + cb);
            cpa16(d0 + (6400 + rb*20 + cb)*4,   BL + (size_t)(bn*64 + rb)*KQ + kq0 + cb);
        }
        CP_COMMIT();
    };

    int hh[2][4][4], xx[2][4][4];
    #pragma unroll
    for (int mt = 0; mt < 2; mt++)
        #pragma unroll
        for (int nt = 0; nt < 4; nt++)
            #pragma unroll
            for (int c = 0; c < 4; c++){ hh[mt][nt][c] = 0; xx[mt][nt][c] = 0; }

    const uint32_t lrow = (lane & 15), lcolo = ((lane >> 4) << 2);
    const int nT = 16;

    issue(0);
    for (int t = 0; t < nT; ++t){
        CP_WAIT0();
        __syncthreads();
        if (t + 1 < nT) issue(t + 1);

        const uint32_t st = sb + ((t & 1)*GI_STAGE)*4;
        #pragma unroll
        for (int kk = 0; kk < 2; kk++){
            const uint32_t fo = (lrow*20 + kk*8 + lcolo)*4;
            uint32_t aH_[2][4], aL_[2][4];
            #pragma unroll
            for (int mt = 0; mt < 2; mt++){
                const uint32_t ra = st + ((wm*32 + mt*16)*20)*4 + fo;
                LDSM4(aH_[mt][0], aH_[mt][1], aH_[mt][2], aH_[mt][3], ra);
                LDSM4(aL_[mt][0], aL_[mt][1], aL_[mt][2], aL_[mt][3], ra + 2560*4);
            }
            #pragma unroll
            for (int ntp = 0; ntp < 2; ntp++){
                const uint32_t rb = st + (5120 + (wn*32 + ntp*16)*20)*4 + fo;
                uint32_t bH0, bH1, bH2, bH3, bL0, bL1, bL2, bL3;
                LDSM4(bH0, bH1, bH2, bH3, rb);
                LDSM4(bL0, bL1, bL2, bL3, rb + 1280*4);
                #pragma unroll
                for (int mt = 0; mt < 2; mt++){
                    imma32(hh[mt][2*ntp],   aH_[mt], bH0, bH2);
                    imma32(xx[mt][2*ntp],   aH_[mt], bL0, bL2);
                    imma32(xx[mt][2*ntp],   aL_[mt], bH0, bH2);
                    imma32(hh[mt][2*ntp+1], aH_[mt], bH1, bH3);
                    imma32(xx[mt][2*ntp+1], aH_[mt], bL1, bL3);
                    imma32(xx[mt][2*ntp+1], aL_[mt], bH1, bH3);
                }
            }
        }
    }

    #pragma unroll
    for (int mt = 0; mt < 2; mt++)
        #pragma unroll
        for (int nt = 0; nt < 4; nt++){
            const int col0 = bn*64 + wn*32 + nt*8 + ((lane&3)<<1);
            const float t0 = SB[col0], t1 = SB[col0+1];
            #pragma unroll
            for (int half = 0; half < 2; half++){
                const int row = bm*128 + wm*32 + mt*16 + (lane>>2) + half*8;
                const float s = SA[(size_t)bz*Mx + row];
                const float c0 = s*t0*(1.f/16129.f), c1 = s*t1*(1.f/16129.f);
                const float v0 = c0*((float)hh[mt][nt][2*half]   + (float)xx[mt][nt][2*half]  *(1.f/128.f));
                const float v1 = c1*((float)hh[mt][nt][2*half+1] + (float)xx[mt][nt][2*half+1]*(1.f/128.f));
                if (MODE == 1){
                    const int h = col0 / 192;
                    const int rr = col0 - 192*h;
                    const size_t mi = (size_t)((bz*HH + h)*MM + row);
                    if (rr < 64)
                        *(float2*)&g_Q[mi*KHD + rr]       = make_float2(v0, v1);
                    else if (rr < 128)
                        *(float2*)&g_K[mi*KHD + rr - 64]  = make_float2(v0, v1);
                    else
                        *(float2*)&g_V[mi*KHD + rr - 128] = make_float2(v0, v1);
                } else {
                    *(float2*)&C[(size_t)row*Nx + col0] = make_float2(v0, v1);
                }
            }
        }
}

// ---------------------------------------------------------------------------
// Flash attention: S = QK^T int8 Ozaki, softmax fp32, P.V bf16 3x (R12).
// ---------------------------------------------------------------------------
#define A_STAGE 7232
#define ATTN_SMEM_BYTES (3*A_STAGE*4)

__global__ __launch_bounds__(256, 2) void attn_tc()
{
    extern __shared__ uint32_t smu[];
    const uint32_t sb = smem_u32(smu);

    const int tid = threadIdx.x, lane = tid & 31, wid = tid >> 5;
    const int qt = gridDim.x - 1 - blockIdx.x;
    const int bh = blockIdx.y;
    const int q0 = qt * 128;

    const uint32_t* KH_g = g_KH + (size_t)bh*MM*16;
    const uint32_t* KL_g = g_KL + (size_t)bh*MM*16;
    const float*    KS_g = g_KS + (size_t)bh*MM;
    const uint32_t* Vh_g = g_Vph + (size_t)bh*KHD*(MM/2);
    const uint32_t* Vl_g = g_Vpl + (size_t)bh*KHD*(MM/2);

    const int rA = wid*16 + (lane>>2);
    const size_t qrow = (size_t)bh*MM + q0 + rA;

    uint32_t qH[2][4], qL[2][4];
    #pragma unroll
    for (int ks = 0; ks < 2; ks++){
        int kq = ks*8 + (lane & 3);
        qH[ks][0] = g_QH[qrow*16 + kq];
        qH[ks][1] = g_QH[(qrow+8)*16 + kq];
        qH[ks][2] = g_QH[qrow*16 + kq + 4];
        qH[ks][3] = g_QH[(qrow+8)*16 + kq + 4];
        qL[ks][0] = g_QL[qrow*16 + kq];
        qL[ks][1] = g_QL[(qrow+8)*16 + kq];
        qL[ks][2] = g_QL[qrow*16 + kq + 4];
        qL[ks][3] = g_QL[(qrow+8)*16 + kq + 4];
    }
    const float cq0 = g_QS[qrow]   * (0.125f/16129.f);
    const float cq1 = g_QS[qrow+8] * (0.125f/16129.f);

    auto issue = [&](int kt){
        const int k0 = kt*64;
        const uint32_t d0 = sb + ((kt % 3)*A_STAGE)*4;
        {
            int key = tid >> 2, c4 = (tid & 3) << 2;
            cpa16(d0 + (key*20 + c4)*4,          KH_g + (size_t)(k0+key)*16 + c4);
            cpa16(d0 + (1280 + key*20 + c4)*4,   KL_g + (size_t)(k0+key)*16 + c4);
        }
        if (tid < 16)
            cpa16(d0 + (2560 + tid*4)*4, KS_g + k0 + tid*4);
        {
            int dr = tid >> 3, mc = (tid & 7) << 2;
            cpa16(d0 + (2624 + dr*36 + mc)*4,       Vh_g + (size_t)dr*(MM/2) + (k0>>1) + mc);
            cpa16(d0 + (2624 + (dr+32)*36 + mc)*4,  Vh_g + (size_t)(dr+32)*(MM/2) + (k0>>1) + mc);
            cpa16(d0 + (4928 + dr*36 + mc)*4,       Vl_g + (size_t)dr*(MM/2) + (k0>>1) + mc);
            cpa16(d0 + (4928 + (dr+32)*36 + mc)*4,  Vl_g + (size_t)(dr+32)*(MM/2) + (k0>>1) + mc);
        }
        CP_COMMIT();
    };

    float o[8][4];
    #pragma unroll
    for (int nt = 0; nt < 8; nt++)
        #pragma unroll
        for (int c = 0; c < 4; c++) o[nt][c] = 0.f;
    float m_run[2] = {-1e30f, -1e30f};
    float l_run[2] = {0.f, 0.f};

    const uint32_t lrow = (lane & 15), lcol = ((lane >> 4) << 2);
    const int ktEnd = 2*qt + 1;

    issue(0);
    issue(1);
    for (int kt = 0; kt <= ktEnd; kt++){
        const int k0 = kt*64;
        if (kt < ktEnd) CP_WAIT1(); else CP_WAIT0();
        __syncthreads();
        if (kt + 2 <= ktEnd) issue(kt + 2);

        const uint32_t st = sb + ((kt % 3)*A_STAGE)*4;
        const int stage_u32 = (kt % 3)*A_STAGE;

        int hh[8][4], xx[8][4];
        #pragma unroll
        for (int nt = 0; nt < 8; nt++)
            #pragma unroll
            for (int c = 0; c < 4; c++){ hh[nt][c] = 0; xx[nt][c] = 0; }

        #pragma unroll
        for (int ks = 0; ks < 2; ks++){
            const uint32_t fo = (lrow*20 + ks*8 + lcol)*4;
            #pragma unroll
            for (int ntp = 0; ntp < 4; ntp++){
                const uint32_t ra = st + ((ntp*16)*20)*4 + fo;
                uint32_t h0, h1, h2, h3, l0, l1, l2, l3;
                LDSM4(h0, h1, h2, h3, ra);
                LDSM4(l0, l1, l2, l3, ra + 1280*4);
                imma32(hh[2*ntp],   qH[ks], h0, h2);
                imma32(xx[2*ntp],   qH[ks], l0, l2);
                imma32(xx[2*ntp],   qL[ks], h0, h2);
                imma32(hh[2*ntp+1], qH[ks], h1, h3);
                imma32(xx[2*ntp+1], qH[ks], l1, l3);
                imma32(xx[2*ntp+1], qL[ks], h1, h3);
            }
        }

        const bool needMask = (kt >= 2*qt);
        float s[8][4];
        #pragma unroll
        for (int nt = 0; nt < 8; nt++){
            const int keyA = nt*8 + ((lane&3)<<1);
            const float skA = ((const float*)smu)[stage_u32 + 2560 + keyA];
            const float skB = ((const float*)smu)[stage_u32 + 2560 + keyA + 1];
            #pragma unroll
            for (int c = 0; c < 4; c++){
                const float rs = (c < 2) ? cq0 : cq1;
                const float sk = (c & 1) ? skB : skA;
                float v = rs * sk * ((float)hh[nt][c] + (float)xx[nt][c]*(1.f/128.f));
                if (needMask){
                    int rowL = wid*16 + (lane>>2) + ((c>>1)<<3);
                    int colL = keyA + (c&1);
                    if (k0 + colL > q0 + rowL) v = -1e30f;
                }
                s[nt][c] = v;
            }
        }

        #pragma unroll
        for (int hf = 0; hf < 2; hf++){
            float rm = -1e30f;
            #pragma unroll
            for (int nt = 0; nt < 8; nt++)
                rm = fmaxf(rm, fmaxf(s[nt][2*hf], s[nt][2*hf+1]));
            rm = fmaxf(rm, __shfl_xor_sync(0xffffffffu, rm, 1));
            rm = fmaxf(rm, __shfl_xor_sync(0xffffffffu, rm, 2));
            float mn  = fmaxf(m_run[hf], rm);
            float scl = __expf(m_run[hf] - mn);
            float psum = 0.f;
            #pragma unroll
            for (int nt = 0; nt < 8; nt++){
                float p0 = __expf(s[nt][2*hf]   - mn);
                float p1 = __expf(s[nt][2*hf+1] - mn);
                s[nt][2*hf] = p0; s[nt][2*hf+1] = p1;
                psum += p0 + p1;
            }
            psum += __shfl_xor_sync(0xffffffffu, psum, 1);
            psum += __shfl_xor_sync(0xffffffffu, psum, 2);
            l_run[hf] = l_run[hf]*scl + psum;
            m_run[hf] = mn;
            #pragma unroll
            for (int nt = 0; nt < 8; nt++){
                o[nt][2*hf]   *= scl;
                o[nt][2*hf+1] *= scl;
            }
        }

        #pragma unroll
        for (int kk = 0; kk < 4; kk++){
            uint32_t ah[4], al[4];
            float rx, ry;
            ah[0] = bsplit(s[2*kk][0],   s[2*kk][1],   rx, ry); al[0] = bpack(rx, ry);
            ah[1] = bsplit(s[2*kk][2],   s[2*kk][3],   rx, ry); al[1] = bpack(rx, ry);
            ah[2] = bsplit(s[2*kk+1][0], s[2*kk+1][1], rx, ry); al[2] = bpack(rx, ry);
            ah[3] = bsplit(s[2*kk+1][2], s[2*kk+1][3], rx, ry); al[3] = bpack(rx, ry);
            const uint32_t fo = (lrow*36 + kk*8 + lcol)*4;
            #pragma unroll
            for (int ntp = 0; ntp < 4; ntp++){
                const uint32_t rv = st + (2624 + (ntp*16)*36)*4 + fo;
                uint32_t h0, h1, h2, h3, l0, l1, l2, l3;
                LDSM4(h0, h1, h2, h3, rv);
                LDSM4(l0, l1, l2, l3, rv + 2304*4);
                mma16(o[2*ntp],   ah, h0, h2);
                mma16(o[2*ntp],   ah, l0, l2);
                mma16(o[2*ntp],   al, h0, h2);
                mma16(o[2*ntp+1], ah, h1, h3);
                mma16(o[2*ntp+1], ah, l1, l3);
                mma16(o[2*ntp+1], al, h1, h3);
            }
        }
    }

    const int b = bh >> 4, h = bh & 15;
    const float inv0 = 1.f / l_run[0], inv1 = 1.f / l_run[1];
    const int m0 = q0 + rA;
    #pragma unroll
    for (int nt = 0; nt < 8; nt++){
        int d0 = nt*8 + ((lane&3)<<1);
        *(float2*)&g_O[(size_t)(b*MM + m0)*DD + h*64 + d0] =
            make_float2(o[nt][0]*inv0, o[nt][1]*inv0);
        *(float2*)&g_O[(size_t)(b*MM + m0 + 8)*DD + h*64 + d0] =
            make_float2(o[nt][2]*inv1, o[nt][3]*inv1);
    }
}

// ---------------------------------------------------------------------------
extern "C" void kernel_launch(void* const* d_in, const int* in_sizes, int n_in,
                              void* d_out, int out_size)
{
    const float* x   = (const float*)d_in[0];
    const float* P_i = (const float*)d_in[1];
    const float* P_o = (const float*)d_in[2];
    float* y = (float*)d_out;

    uint32_t *xH, *xL, *piH, *piL, *poH, *poL, *oH, *oL, *qH, *qL, *kH, *kL;
    float *xS, *piS, *poS, *oS, *qS, *kS, *Q, *K, *O;
    cudaGetSymbolAddress((void**)&xH,  g_xH);  cudaGetSymbolAddress((void**)&xL,  g_xL);
    cudaGetSymbolAddress((void**)&xS,  g_xS);
    cudaGetSymbolAddress((void**)&piH, g_PiH); cudaGetSymbolAddress((void**)&piL, g_PiL);
    cudaGetSymbolAddress((void**)&piS, g_PiS);
    cudaGetSymbolAddress((void**)&poH, g_PoH); cudaGetSymbolAddress((void**)&poL, g_PoL);
    cudaGetSymbolAddress((void**)&poS, g_PoS);
    cudaGetSymbolAddress((void**)&oH,  g_OH);  cudaGetSymbolAddress((void**)&oL,  g_OL);
    cudaGetSymbolAddress((void**)&oS,  g_OS);
    cudaGetSymbolAddress((void**)&qH,  g_QH);  cudaGetSymbolAddress((void**)&qL,  g_QL);
    cudaGetSymbolAddress((void**)&qS,  g_QS);
    cudaGetSymbolAddress((void**)&kH,  g_KH);  cudaGetSymbolAddress((void**)&kL,  g_KL);
    cudaGetSymbolAddress((void**)&kS,  g_KS);
    cudaGetSymbolAddress((void**)&Q,   g_Q);
    cudaGetSymbolAddress((void**)&K,   g_K);
    cudaGetSymbolAddress((void**)&O,   g_O);

    cudaFuncSetAttribute(gemm_i8<1>, cudaFuncAttributeMaxDynamicSharedMemorySize,
                         GI_SMEM_BYTES);
    cudaFuncSetAttribute(gemm_i8<2>, cudaFuncAttributeMaxDynamicSharedMemorySize,
                         GI_SMEM_BYTES);
    cudaFuncSetAttribute(attn_tc, cudaFuncAttributeMaxDynamicSharedMemorySize,
                         ATTN_SMEM_BYTES);

    // 0) quantize inputs
    quant_rows<<<BB*MM, 256>>>(x, xH, xL, xS);
    {
        dim3 b(32, 8);
        colmax2<<<N3/32, b>>>(P_i, piS, N3);
        colmax2<<<DD/32, b>>>(P_o, poS, DD);
    }
    {
        dim3 g(N3/32, 1024/64);
        quant_wT<<<g, 256>>>(P_i, piH, piL, piS, N3);
    }
    {
        dim3 g(DD/32, 1024/64);
        quant_wT<<<g, 256>>>(P_o, poH, poL, poS, DD);
    }
    // 1) QKV projection (int8 Ozaki) -> fp32 Q/K/V
    {
        dim3 grid(N3/64, MM/128, BB);
        gemm_i8<1><<<grid, 256, GI_SMEM_BYTES>>>(xH, xL, piH, piL, xS, piS,
                                                 nullptr, MM, N3);
    }
    // 1.5) quantize Q/K rows (int8 pairs), split V to bf16 pairs
    quant_qk64<<<(BB*HH*MM)/8, 256>>>(Q, qH, qL, qS);
    quant_qk64<<<(BB*HH*MM)/8, 256>>>(K, kH, kL, kS);
    {
        dim3 g(MM/64, BB*HH);
        split_vT<<<g, 256>>>();
    }
    // 2) causal flash attention (int8 S, bf16 PV) -> fp32 O
    {
        dim3 grid(MM/128, BB*HH);
        attn_tc<<<grid, 256, ATTN_SMEM_BYTES>>>();
    }
    // 2.5) quantize O rows
    quant_rows<<<BB*MM, 256>>>(O, oH, oL, oS);
    // 3) output projection (int8 Ozaki)
    {
        dim3 grid(DD/64, (BB*MM)/128, 1);
        gemm_i8<2><<<grid, 256, GI_SMEM_BYTES>>>(oH, oL, poH, poL, oS, poS,
                                                 y, BB*MM, DD);
    }
}

// round 17
// speedup vs baseline: 1.1317x; 1.0120x over previous
#include <cuda_runtime.h>
#include <cuda_bf16.h>
#include <math.h>
#include <stdint.h>

#define BB 8
#define MM 1024
#define DD 1024
#define HH 16
#define KHD 64
#define N3 3072
#define KQ 256   // k-quads (4 int8) for K=1024

// fp32 intermediates
__device__ float g_Q[BB*HH*MM*KHD];
__device__ float g_K[BB*HH*MM*KHD];
__device__ float g_V[BB*HH*MM*KHD];
__device__ float g_O[BB*MM*DD];

// int8 Ozaki operands for projections: u32 = 4 consecutive-k int8
__device__ uint32_t g_xH [BB*MM*KQ],  g_xL [BB*MM*KQ];
__device__ float    g_xS [BB*MM];
__device__ uint32_t g_PiH[N3*KQ],     g_PiL[N3*KQ];
__device__ float    g_PiS[N3];
__device__ uint32_t g_PoH[DD*KQ],     g_PoL[DD*KQ];
__device__ float    g_PoS[DD];
__device__ uint32_t g_OH [BB*MM*KQ],  g_OL [BB*MM*KQ];
__device__ float    g_OS [BB*MM];

// int8 attention operands (rows of 64 -> 16 kq)
__device__ uint32_t g_QH[BB*HH*MM*16], g_QL[BB*HH*MM*16];
__device__ float    g_QS[BB*HH*MM];
__device__ uint32_t g_KH[BB*HH*MM*16], g_KL[BB*HH*MM*16];
__device__ float    g_KS[BB*HH*MM];

// bf16 V operands (packed bf16x2 key-pairs, transposed [bh][d][mp])
__device__ uint32_t g_Vph[BB*HH*KHD*(MM/2)], g_Vpl[BB*HH*KHD*(MM/2)];

// ---------------------------------------------------------------------------
__device__ __forceinline__ uint32_t bpack(float x, float y){
    __nv_bfloat162 h = __floats2bfloat162_rn(x, y);
    return *reinterpret_cast<uint32_t*>(&h);
}
__device__ __forceinline__ uint32_t bsplit(float x, float y, float& rx, float& ry){
    __nv_bfloat162 h = __floats2bfloat162_rn(x, y);
    rx = x - __low2float(h);
    ry = y - __high2float(h);
    return *reinterpret_cast<uint32_t*>(&h);
}
__device__ __forceinline__ void mma16(float* d, const uint32_t* a,
                                      uint32_t b0, uint32_t b1){
    asm volatile("mma.sync.aligned.m16n8k16.row.col.f32.bf16.bf16.f32 "
        "{%0,%1,%2,%3},{%4,%5,%6,%7},{%8,%9},{%0,%1,%2,%3};"
        : "+f"(d[0]), "+f"(d[1]), "+f"(d[2]), "+f"(d[3])
        : "r"(a[0]), "r"(a[1]), "r"(a[2]), "r"(a[3]), "r"(b0), "r"(b1));
}
__device__ __forceinline__ void imma32(int* d, const uint32_t* a,
                                       uint32_t b0, uint32_t b1){
    asm volatile("mma.sync.aligned.m16n8k32.row.col.s32.s8.s8.s32 "
        "{%0,%1,%2,%3},{%4,%5,%6,%7},{%8,%9},{%0,%1,%2,%3};"
        : "+r"(d[0]), "+r"(d[1]), "+r"(d[2]), "+r"(d[3])
        : "r"(a[0]), "r"(a[1]), "r"(a[2]), "r"(a[3]), "r"(b0), "r"(b1));
}
__device__ __forceinline__ uint32_t smem_u32(const void* p){
    uint32_t a;
    asm("{ .reg .u64 t; cvta.to.shared.u64 t, %1; cvt.u32.u64 %0, t; }"
        : "=r"(a) : "l"(p));
    return a;
}
__device__ __forceinline__ void cpa16(uint32_t dst, const void* src){
    asm volatile("cp.async.ca.shared.global [%0], [%1], 16;"
                 :: "r"(dst), "l"(src) : "memory");
}
#define CP_COMMIT() asm volatile("cp.async.commit_group;" ::: "memory")
#define CP_WAIT1()  asm volatile("cp.async.wait_group 1;" ::: "memory")
#define CP_WAIT0()  asm volatile("cp.async.wait_group 0;" ::: "memory")
#define LDSM4(r0,r1,r2,r3,addr) asm volatile( \
    "ldmatrix.sync.aligned.m8n8.x4.shared.b16 {%0,%1,%2,%3}, [%4];" \
    : "=r"(r0), "=r"(r1), "=r"(r2), "=r"(r3) : "r"(addr))

__device__ __forceinline__ uint32_t pack4(int a, int b, int c, int d){
    return (uint32_t)(uint8_t)(int8_t)a        | ((uint32_t)(uint8_t)(int8_t)b << 8)
         | ((uint32_t)(uint8_t)(int8_t)c << 16)| ((uint32_t)(uint8_t)(int8_t)d << 24);
}
__device__ __forceinline__ void q2(float f, float inv, int& h, int& l){
    float q = f * inv;
    h = __float2int_rn(q);
    l = __float2int_rn((q - (float)h) * 128.f);
}

// ---------------------------------------------------------------------------
// Quantization pre-passes
// ---------------------------------------------------------------------------
__global__ void quant_rows(const float* __restrict__ src,
                           uint32_t* __restrict__ H, uint32_t* __restrict__ L,
                           float* __restrict__ S){
    __shared__ float red[256];
    const int row = blockIdx.x, tid = threadIdx.x;
    float4 v = ((const float4*)(src + (size_t)row*1024))[tid];
    float m = fmaxf(fmaxf(fabsf(v.x), fabsf(v.y)), fmaxf(fabsf(v.z), fabsf(v.w)));
    red[tid] = m; __syncthreads();
    for (int o = 128; o > 0; o >>= 1){
        if (tid < o) red[tid] = fmaxf(red[tid], red[tid+o]);
        __syncthreads();
    }
    const float s = fmaxf(red[0], 1e-20f);
    const float inv = 127.f / s;
    int h0,l0,h1,l1,h2,l2,h3,l3;
    q2(v.x, inv, h0, l0); q2(v.y, inv, h1, l1);
    q2(v.z, inv, h2, l2); q2(v.w, inv, h3, l3);
    H[(size_t)row*KQ + tid] = pack4(h0,h1,h2,h3);
    L[(size_t)row*KQ + tid] = pack4(l0,l1,l2,l3);
    if (tid == 0) S[row] = s;
}
// coalesced column max: block = 32 columns x 8 k-lanes
__global__ void colmax2(const float* __restrict__ W, float* __restrict__ S, int N){
    __shared__ float red[8][33];
    const int tx = threadIdx.x, ty = threadIdx.y;
    const int n = blockIdx.x*32 + tx;
    float m = 0.f;
    for (int k = ty; k < 1024; k += 8)
        m = fmaxf(m, fabsf(W[(size_t)k*N + n]));
    red[ty][tx] = m;
    __syncthreads();
    if (ty == 0){
        #pragma unroll
        for (int j = 1; j < 8; j++) m = fmaxf(m, red[j][tx]);
        S[n] = fmaxf(m, 1e-20f);
    }
}
__global__ void quant_wT(const float* __restrict__ W,
                         uint32_t* __restrict__ H, uint32_t* __restrict__ L,
                         const float* __restrict__ S, int N){
    __shared__ float tile[64][33];
    const int n0 = blockIdx.x*32, k0 = blockIdx.y*64, tid = threadIdx.x;
    #pragma unroll
    for (int it = 0; it < 8; it++){
        int idx = tid + it*256;
        int kr = idx >> 5, nc = idx & 31;
        tile[kr][nc] = W[(size_t)(k0+kr)*N + n0 + nc];
    }
    __syncthreads();
    const int nl = tid >> 3, kq8 = tid & 7;
    const float inv = 127.f / S[n0 + nl];
    #pragma unroll
    for (int j = 0; j < 2; j++){
        int kq = kq8*2 + j;
        int h0,l0,h1,l1,h2,l2,h3,l3;
        q2(tile[kq*4+0][nl], inv, h0, l0);
        q2(tile[kq*4+1][nl], inv, h1, l1);
        q2(tile[kq*4+2][nl], inv, h2, l2);
        q2(tile[kq*4+3][nl], inv, h3, l3);
        H[(size_t)(n0+nl)*KQ + blockIdx.y*16 + kq] = pack4(h0,h1,h2,h3);
        L[(size_t)(n0+nl)*KQ + blockIdx.y*16 + kq] = pack4(l0,l1,l2,l3);
    }
}
// per-row-of-64 quantizer for Q/K: warp per row, 8 rows per block
__global__ void quant_qk64(const float* __restrict__ src,
                           uint32_t* __restrict__ H, uint32_t* __restrict__ L,
                           float* __restrict__ S){
    __shared__ float buf[8][64];
    __shared__ float sc[8];
    const int w = threadIdx.x >> 5, l = threadIdx.x & 31;
    const size_t row = (size_t)blockIdx.x*8 + w;
    float2 v = ((const float2*)(src + row*64))[l];
    buf[w][2*l]   = v.x;
    buf[w][2*l+1] = v.y;
    float m = fmaxf(fabsf(v.x), fabsf(v.y));
    #pragma unroll
    for (int o = 16; o > 0; o >>= 1)
        m = fmaxf(m, __shfl_xor_sync(0xffffffffu, m, o));
    if (l == 0){ float s = fmaxf(m, 1e-20f); sc[w] = s; S[row] = s; }
    __syncwarp();
    if (l < 16){
        const float inv = 127.f / sc[w];
        int h0,l0,h1,l1,h2,l2,h3,l3;
        q2(buf[w][4*l+0], inv, h0, l0);
        q2(buf[w][4*l+1], inv, h1, l1);
        q2(buf[w][4*l+2], inv, h2, l2);
        q2(buf[w][4*l+3], inv, h3, l3);
        H[row*16 + l] = pack4(h0,h1,h2,h3);
        L[row*16 + l] = pack4(l0,l1,l2,l3);
    }
}
// V: g_V [bh][m][64] fp32 -> [bh][d][mp] packed bf16 key-pairs
__global__ void split_vT(){
    __shared__ uint32_t sh[32][65], sl[32][65];
    const int bh = blockIdx.y, mp0 = blockIdx.x*32;
    const float* V = g_V + (size_t)bh*MM*KHD;
    const int tid = threadIdx.x;
    #pragma unroll
    for (int it = 0; it < 8; it++){
        int idx = tid + it*256;
        int mp = idx >> 6, d = idx & 63;
        float a = V[(size_t)(2*(mp0+mp))*KHD + d];
        float b = V[(size_t)(2*(mp0+mp)+1)*KHD + d];
        float rx, ry;
        sh[mp][d] = bsplit(a, b, rx, ry);
        sl[mp][d] = bpack(rx, ry);
    }
    __syncthreads();
    uint32_t* oh = g_Vph + (size_t)bh*KHD*(MM/2);
    uint32_t* ol = g_Vpl + (size_t)bh*KHD*(MM/2);
    #pragma unroll
    for (int it = 0; it < 8; it++){
        int idx = tid + it*256;
        int d = idx >> 5, mpi = idx & 31;
        oh[(size_t)d*(MM/2) + mp0 + mpi] = sh[mpi][d];
        ol[(size_t)d*(MM/2) + mp0 + mpi] = sl[mpi][d];
    }
}

// ---------------------------------------------------------------------------
// int8 Ozaki GEMM: CTA 128m x 64n, k-tile 128 (32 kq), 8 warps as 4m x 2n.
// 8 pipeline iterations (halved barriers vs k-tile 64). 2-stage ring.
// smem per stage (u32): AH[128][36] @0 | AL @4608 | BH[64][36] @9216 |
// BL @11520  = 13824 u32 = 54 KB; 2 stages = 108 KB; 2 CTAs/SM.
// pitch 36 u32 = 144 B: 16B-aligned, LDSM phases 16r mod 128 distinct.
// MODE 1: QKV -> fp32 g_Q/g_K/g_V. MODE 2: proj -> C.
// ---------------------------------------------------------------------------
#define GI_STAGE 13824
#define GI_SMEM_BYTES (2*GI_STAGE*4)

template<int MODE>
__global__ __launch_bounds__(256, 2) void gemm_i8(
    const uint32_t* __restrict__ AH, const uint32_t* __restrict__ AL,
    const uint32_t* __restrict__ BH, const uint32_t* __restrict__ BL,
    const float* __restrict__ SA, const float* __restrict__ SB,
    float* __restrict__ C, int Mx, int Nx)
{
    extern __shared__ uint32_t smg[];
    const uint32_t sb = smem_u32(smg);
    const int tid = threadIdx.x, lane = tid & 31, wid = tid >> 5;
    const int wm = wid >> 1, wn = wid & 1;     // 4m x 2n warp grid
    const int bm = blockIdx.y, bn = blockIdx.x, bz = blockIdx.z;

    const uint32_t* Ah = AH + (size_t)bz * Mx * KQ;
    const uint32_t* Al = AL + (size_t)bz * Mx * KQ;

    auto issue = [&](int t){
        const int kq0 = t << 5;                 // 32 kq per tile
        const uint32_t d0 = sb + ((t & 1)*GI_STAGE)*4;
        #pragma unroll
        for (int it = 0; it < 4; it++){
            int idx = tid + it*256;
            int ra = idx >> 3, ca = (idx & 7) << 2;
            cpa16(d0 + (ra*36 + ca)*4,          Ah + (size_t)(bm*128 + ra)*KQ + kq0 + ca);
            cpa16(d0 + (4608 + ra*36 + ca)*4,   Al + (size_t)(bm*128 + ra)*KQ + kq0 + ca);
        }
        #pragma unroll
        for (int it = 0; it < 2; it++){
            int idx = tid + it*256;
            int rb = idx >> 3, cb = (idx & 7) << 2;
            cpa16(d0 + (9216 + rb*36 + cb)*4,   BH + (size_t)(bn*64 + rb)*KQ + kq0 + cb);
            cpa16(d0 + (11520 + rb*36 + cb)*4,  BL + (size_t)(bn*64 + rb)*KQ + kq0 + cb);
        }
        CP_COMMIT();
    };

    int hh[2][4][4], xx[2][4][4];
    #pragma unroll
    for (int mt = 0; mt < 2; mt++)
        #pragma unroll
        for (int nt = 0; nt < 4; nt++)
            #pragma unroll
            for (int c = 0; c < 4; c++){ hh[mt][nt][c] = 0; xx[mt][nt][c] = 0; }

    const uint32_t lrow = (lane & 15), lcolo = ((lane >> 4) << 2);
    const int nT = 8;                           // K=1024 / 128

    issue(0);
    for (int t = 0; t < nT; ++t){
        CP_WAIT0();
        __syncthreads();
        if (t + 1 < nT) issue(t + 1);

        const uint32_t st = sb + ((t & 1)*GI_STAGE)*4;
        #pragma unroll
        for (int ks = 0; ks < 4; ks++){
            const uint32_t fo = (lrow*36 + ks*8 + lcolo)*4;
            uint32_t aH_[2][4], aL_[2][4];
            #pragma unroll
            for (int mt = 0; mt < 2; mt++){
                const uint32_t ra = st + ((wm*32 + mt*16)*36)*4 + fo;
                LDSM4(aH_[mt][0], aH_[mt][1], aH_[mt][2], aH_[mt][3], ra);
                LDSM4(aL_[mt][0], aL_[mt][1], aL_[mt][2], aL_[mt][3], ra + 4608*4);
            }
            #pragma unroll
            for (int ntp = 0; ntp < 2; ntp++){
                const uint32_t rb = st + (9216 + (wn*32 + ntp*16)*36)*4 + fo;
                uint32_t bH0, bH1, bH2, bH3, bL0, bL1, bL2, bL3;
                LDSM4(bH0, bH1, bH2, bH3, rb);
                LDSM4(bL0, bL1, bL2, bL3, rb + 2304*4);
                #pragma unroll
                for (int mt = 0; mt < 2; mt++){
                    imma32(hh[mt][2*ntp],   aH_[mt], bH0, bH2);
                    imma32(xx[mt][2*ntp],   aH_[mt], bL0, bL2);
                    imma32(xx[mt][2*ntp],   aL_[mt], bH0, bH2);
                    imma32(hh[mt][2*ntp+1], aH_[mt], bH1, bH3);
                    imma32(xx[mt][2*ntp+1], aH_[mt], bL1, bL3);
                    imma32(xx[mt][2*ntp+1], aL_[mt], bH1, bH3);
                }
            }
        }
    }

    #pragma unroll
    for (int mt = 0; mt < 2; mt++)
        #pragma unroll
        for (int nt = 0; nt < 4; nt++){
            const int col0 = bn*64 + wn*32 + nt*8 + ((lane&3)<<1);
            const float t0 = SB[col0], t1 = SB[col0+1];
            #pragma unroll
            for (int half = 0; half < 2; half++){
                const int row = bm*128 + wm*32 + mt*16 + (lane>>2) + half*8;
                const float s = SA[(size_t)bz*Mx + row];
                const float c0 = s*t0*(1.f/16129.f), c1 = s*t1*(1.f/16129.f);
                const float v0 = c0*((float)hh[mt][nt][2*half]   + (float)xx[mt][nt][2*half]  *(1.f/128.f));
                const float v1 = c1*((float)hh[mt][nt][2*half+1] + (float)xx[mt][nt][2*half+1]*(1.f/128.f));
                if (MODE == 1){
                    const int h = col0 / 192;
                    const int rr = col0 - 192*h;
                    const size_t mi = (size_t)((bz*HH + h)*MM + row);
                    if (rr < 64)
                        *(float2*)&g_Q[mi*KHD + rr]       = make_float2(v0, v1);
                    else if (rr < 128)
                        *(float2*)&g_K[mi*KHD + rr - 64]  = make_float2(v0, v1);
                    else
                        *(float2*)&g_V[mi*KHD + rr - 128] = make_float2(v0, v1);
                } else {
                    *(float2*)&C[(size_t)row*Nx + col0] = make_float2(v0, v1);
                }
            }
        }
}

// ---------------------------------------------------------------------------
// Flash attention: S = QK^T int8 Ozaki, softmax fp32, P.V bf16 3x (R12).
// ---------------------------------------------------------------------------
#define A_STAGE 7232
#define ATTN_SMEM_BYTES (3*A_STAGE*4)

__global__ __launch_bounds__(256, 2) void attn_tc()
{
    extern __shared__ uint32_t smu[];
    const uint32_t sb = smem_u32(smu);

    const int tid = threadIdx.x, lane = tid & 31, wid = tid >> 5;
    const int qt = gridDim.x - 1 - blockIdx.x;
    const int bh = blockIdx.y;
    const int q0 = qt * 128;

    const uint32_t* KH_g = g_KH + (size_t)bh*MM*16;
    const uint32_t* KL_g = g_KL + (size_t)bh*MM*16;
    const float*    KS_g = g_KS + (size_t)bh*MM;
    const uint32_t* Vh_g = g_Vph + (size_t)bh*KHD*(MM/2);
    const uint32_t* Vl_g = g_Vpl + (size_t)bh*KHD*(MM/2);

    const int rA = wid*16 + (lane>>2);
    const size_t qrow = (size_t)bh*MM + q0 + rA;

    uint32_t qH[2][4], qL[2][4];
    #pragma unroll
    for (int ks = 0; ks < 2; ks++){
        int kq = ks*8 + (lane & 3);
        qH[ks][0] = g_QH[qrow*16 + kq];
        qH[ks][1] = g_QH[(qrow+8)*16 + kq];
        qH[ks][2] = g_QH[qrow*16 + kq + 4];
        qH[ks][3] = g_QH[(qrow+8)*16 + kq + 4];
        qL[ks][0] = g_QL[qrow*16 + kq];
        qL[ks][1] = g_QL[(qrow+8)*16 + kq];
        qL[ks][2] = g_QL[qrow*16 + kq + 4];
        qL[ks][3] = g_QL[(qrow+8)*16 + kq + 4];
    }
    const float cq0 = g_QS[qrow]   * (0.125f/16129.f);
    const float cq1 = g_QS[qrow+8] * (0.125f/16129.f);

    auto issue = [&](int kt){
        const int k0 = kt*64;
        const uint32_t d0 = sb + ((kt % 3)*A_STAGE)*4;
        {
            int key = tid >> 2, c4 = (tid & 3) << 2;
            cpa16(d0 + (key*20 + c4)*4,          KH_g + (size_t)(k0+key)*16 + c4);
            cpa16(d0 + (1280 + key*20 + c4)*4,   KL_g + (size_t)(k0+key)*16 + c4);
        }
        if (tid < 16)
            cpa16(d0 + (2560 + tid*4)*4, KS_g + k0 + tid*4);
        {
            int dr = tid >> 3, mc = (tid & 7) << 2;
            cpa16(d0 + (2624 + dr*36 + mc)*4,       Vh_g + (size_t)dr*(MM/2) + (k0>>1) + mc);
            cpa16(d0 + (2624 + (dr+32)*36 + mc)*4,  Vh_g + (size_t)(dr+32)*(MM/2) + (k0>>1) + mc);
            cpa16(d0 + (4928 + dr*36 + mc)*4,       Vl_g + (size_t)dr*(MM/2) + (k0>>1) + mc);
            cpa16(d0 + (4928 + (dr+32)*36 + mc)*4,  Vl_g + (size_t)(dr+32)*(MM/2) + (k0>>1) + mc);
        }
        CP_COMMIT();
    };

    float o[8][4];
    #pragma unroll
    for (int nt = 0; nt < 8; nt++)
        #pragma unroll
        for (int c = 0; c < 4; c++) o[nt][c] = 0.f;
    float m_run[2] = {-1e30f, -1e30f};
    float l_run[2] = {0.f, 0.f};

    const uint32_t lrow = (lane & 15), lcol = ((lane >> 4) << 2);
    const int ktEnd = 2*qt + 1;

    issue(0);
    issue(1);
    for (int kt = 0; kt <= ktEnd; kt++){
        const int k0 = kt*64;
        if (kt < ktEnd) CP_WAIT1(); else CP_WAIT0();
        __syncthreads();
        if (kt + 2 <= ktEnd) issue(kt + 2);

        const uint32_t st = sb + ((kt % 3)*A_STAGE)*4;
        const int stage_u32 = (kt % 3)*A_STAGE;

        int hh[8][4], xx[8][4];
        #pragma unroll
        for (int nt = 0; nt < 8; nt++)
            #pragma unroll
            for (int c = 0; c < 4; c++){ hh[nt][c] = 0; xx[nt][c] = 0; }

        #pragma unroll
        for (int ks = 0; ks < 2; ks++){
            const uint32_t fo = (lrow*20 + ks*8 + lcol)*4;
            #pragma unroll
            for (int ntp = 0; ntp < 4; ntp++){
                const uint32_t ra = st + ((ntp*16)*20)*4 + fo;
                uint32_t h0, h1, h2, h3, l0, l1, l2, l3;
                LDSM4(h0, h1, h2, h3, ra);
                LDSM4(l0, l1, l2, l3, ra + 1280*4);
                imma32(hh[2*ntp],   qH[ks], h0, h2);
                imma32(xx[2*ntp],   qH[ks], l0, l2);
                imma32(xx[2*ntp],   qL[ks], h0, h2);
                imma32(hh[2*ntp+1], qH[ks], h1, h3);
                imma32(xx[2*ntp+1], qH[ks], l1, l3);
                imma32(xx[2*ntp+1], qL[ks], h1, h3);
            }
        }

        const bool needMask = (kt >= 2*qt);
        float s[8][4];
        #pragma unroll
        for (int nt = 0; nt < 8; nt++){
            const int keyA = nt*8 + ((lane&3)<<1);
            const float skA = ((const float*)smu)[stage_u32 + 2560 + keyA];
            const float skB = ((const float*)smu)[stage_u32 + 2560 + keyA + 1];
            #pragma unroll
            for (int c = 0; c < 4; c++){
                const float rs = (c < 2) ? cq0 : cq1;
                const float sk = (c & 1) ? skB : skA;
                float v = rs * sk * ((float)hh[nt][c] + (float)xx[nt][c]*(1.f/128.f));
                if (needMask){
                    int rowL = wid*16 + (lane>>2) + ((c>>1)<<3);
                    int colL = keyA + (c&1);
                    if (k0 + colL > q0 + rowL) v = -1e30f;
                }
                s[nt][c] = v;
            }
        }

        #pragma unroll
        for (int hf = 0; hf < 2; hf++){
            float rm = -1e30f;
            #pragma unroll
            for (int nt = 0; nt < 8; nt++)
                rm = fmaxf(rm, fmaxf(s[nt][2*hf], s[nt][2*hf+1]));
            rm = fmaxf(rm, __shfl_xor_sync(0xffffffffu, rm, 1));
            rm = fmaxf(rm, __shfl_xor_sync(0xffffffffu, rm, 2));
            float mn  = fmaxf(m_run[hf], rm);
            float scl = __expf(m_run[hf] - mn);
            float psum = 0.f;
            #pragma unroll
            for (int nt = 0; nt < 8; nt++){
                float p0 = __expf(s[nt][2*hf]   - mn);
                float p1 = __expf(s[nt][2*hf+1] - mn);
                s[nt][2*hf] = p0; s[nt][2*hf+1] = p1;
                psum += p0 + p1;
            }
            psum += __shfl_xor_sync(0xffffffffu, psum, 1);
            psum += __shfl_xor_sync(0xffffffffu, psum, 2);
            l_run[hf] = l_run[hf]*scl + psum;
            m_run[hf] = mn;
            #pragma unroll
            for (int nt = 0; nt < 8; nt++){
                o[nt][2*hf]   *= scl;
                o[nt][2*hf+1] *= scl;
            }
        }

        #pragma unroll
        for (int kk = 0; kk < 4; kk++){
            uint32_t ah[4], al[4];
            float rx, ry;
            ah[0] = bsplit(s[2*kk][0],   s[2*kk][1],   rx, ry); al[0] = bpack(rx, ry);
            ah[1] = bsplit(s[2*kk][2],   s[2*kk][3],   rx, ry); al[1] = bpack(rx, ry);
            ah[2] = bsplit(s[2*kk+1][0], s[2*kk+1][1], rx, ry); al[2] = bpack(rx, ry);
            ah[3] = bsplit(s[2*kk+1][2], s[2*kk+1][3], rx, ry); al[3] = bpack(rx, ry);
            const uint32_t fo = (lrow*36 + kk*8 + lcol)*4;
            #pragma unroll
            for (int ntp = 0; ntp < 4; ntp++){
                const uint32_t rv = st + (2624 + (ntp*16)*36)*4 + fo;
                uint32_t h0, h1, h2, h3, l0, l1, l2, l3;
                LDSM4(h0, h1, h2, h3, rv);
                LDSM4(l0, l1, l2, l3, rv + 2304*4);
                mma16(o[2*ntp],   ah, h0, h2);
                mma16(o[2*ntp],   ah, l0, l2);
                mma16(o[2*ntp],   al, h0, h2);
                mma16(o[2*ntp+1], ah, h1, h3);
                mma16(o[2*ntp+1], ah, l1, l3);
                mma16(o[2*ntp+1], al, h1, h3);
            }
        }
    }

    const int b = bh >> 4, h = bh & 15;
    const float inv0 = 1.f / l_run[0], inv1 = 1.f / l_run[1];
    const int m0 = q0 + rA;
    #pragma unroll
    for (int nt = 0; nt < 8; nt++){
        int d0 = nt*8 + ((lane&3)<<1);
        *(float2*)&g_O[(size_t)(b*MM + m0)*DD + h*64 + d0] =
            make_float2(o[nt][0]*inv0, o[nt][1]*inv0);
        *(float2*)&g_O[(size_t)(b*MM + m0 + 8)*DD + h*64 + d0] =
            make_float2(o[nt][2]*inv1, o[nt][3]*inv1);
    }
}

// ---------------------------------------------------------------------------
extern "C" void kernel_launch(void* const* d_in, const int* in_sizes, int n_in,
                              void* d_out, int out_size)
{
    const float* x   = (const float*)d_in[0];
    const float* P_i = (const float*)d_in[1];
    const float* P_o = (const float*)d_in[2];
    float* y = (float*)d_out;

    uint32_t *xH, *xL, *piH, *piL, *poH, *poL, *oH, *oL, *qH, *qL, *kH, *kL;
    float *xS, *piS, *poS, *oS, *qS, *kS, *Q, *K, *O;
    cudaGetSymbolAddress((void**)&xH,  g_xH);  cudaGetSymbolAddress((void**)&xL,  g_xL);
    cudaGetSymbolAddress((void**)&xS,  g_xS);
    cudaGetSymbolAddress((void**)&piH, g_PiH); cudaGetSymbolAddress((void**)&piL, g_PiL);
    cudaGetSymbolAddress((void**)&piS, g_PiS);
    cudaGetSymbolAddress((void**)&poH, g_PoH); cudaGetSymbolAddress((void**)&poL, g_PoL);
    cudaGetSymbolAddress((void**)&poS, g_PoS);
    cudaGetSymbolAddress((void**)&oH,  g_OH);  cudaGetSymbolAddress((void**)&oL,  g_OL);
    cudaGetSymbolAddress((void**)&oS,  g_OS);
    cudaGetSymbolAddress((void**)&qH,  g_QH);  cudaGetSymbolAddress((void**)&qL,  g_QL);
    cudaGetSymbolAddress((void**)&qS,  g_QS);
    cudaGetSymbolAddress((void**)&kH,  g_KH);  cudaGetSymbolAddress((void**)&kL,  g_KL);
    cudaGetSymbolAddress((void**)&kS,  g_KS);
    cudaGetSymbolAddress((void**)&Q,   g_Q);
    cudaGetSymbolAddress((void**)&K,   g_K);
    cudaGetSymbolAddress((void**)&O,   g_O);

    cudaFuncSetAttribute(gemm_i8<1>, cudaFuncAttributeMaxDynamicSharedMemorySize,
                         GI_SMEM_BYTES);
    cudaFuncSetAttribute(gemm_i8<2>, cudaFuncAttributeMaxDynamicSharedMemorySize,
                         GI_SMEM_BYTES);
    cudaFuncSetAttribute(attn_tc, cudaFuncAttributeMaxDynamicSharedMemorySize,
                         ATTN_SMEM_BYTES);

    // 0) quantize inputs
    quant_rows<<<BB*MM, 256>>>(x, xH, xL, xS);
    {
        dim3 b(32, 8);
        colmax2<<<N3/32, b>>>(P_i, piS, N3);
        colmax2<<<DD/32, b>>>(P_o, poS, DD);
    }
    {
        dim3 g(N3/32, 1024/64);
        quant_wT<<<g, 256>>>(P_i, piH, piL, piS, N3);
    }
    {
        dim3 g(DD/32, 1024/64);
        quant_wT<<<g, 256>>>(P_o, poH, poL, poS, DD);
    }
    // 1) QKV projection (int8 Ozaki, k-tile 128) -> fp32 Q/K/V
    {
        dim3 grid(N3/64, MM/128, BB);
        gemm_i8<1><<<grid, 256, GI_SMEM_BYTES>>>(xH, xL, piH, piL, xS, piS,
                                                 nullptr, MM, N3);
    }
    // 1.5) quantize Q/K rows (int8 pairs), split V to bf16 pairs
    quant_qk64<<<(BB*HH*MM)/8, 256>>>(Q, qH, qL, qS);
    quant_qk64<<<(BB*HH*MM)/8, 256>>>(K, kH, kL, kS);
    {
        dim3 g(MM/64, BB*HH);
        split_vT<<<g, 256>>>();
    }
    // 2) causal flash attention (int8 S, bf16 PV) -> fp32 O
    {
        dim3 grid(MM/128, BB*HH);
        attn_tc<<<grid, 256, ATTN_SMEM_BYTES>>>();
    }
    // 2.5) quantize O rows
    quant_rows<<<BB*MM, 256>>>(O, oH, oL, oS);
    // 3) output projection (int8 Ozaki, k-tile 128)
    {
        dim3 grid(DD/64, (BB*MM)/128, 1);
        gemm_i8<2><<<grid, 256, GI_SMEM_BYTES>>>(oH, oL, poH, poL, oS, poS,
                                                 y, BB*MM, DD);
    }
}